// round 3
// baseline (speedup 1.0000x reference)
#include <cuda_runtime.h>
#include <cuda_bf16.h>
#include <cstdint>

// out[8192,4096] = x@W^T + ((x*mask)@A)@B   (fp32, SCALE=1)
#define M_ALL 8192
#define N_ALL 4096
#define K_ALL 4096
#define RNK   32

// ---------------- scratch (__device__ globals; no allocs allowed) ------------
__device__ __align__(256) __nv_bfloat16 g_xhi[(size_t)M_ALL * K_ALL];
__device__ __align__(256) __nv_bfloat16 g_xlo[(size_t)M_ALL * K_ALL];
__device__ __align__(256) __nv_bfloat16 g_whi[(size_t)N_ALL * K_ALL];
__device__ __align__(256) __nv_bfloat16 g_wlo[(size_t)N_ALL * K_ALL];
__device__ __align__(256) __nv_bfloat16 g_tcat[(size_t)M_ALL * 128];   // [Th|Tl|Th|0]
__device__ __align__(256) __nv_bfloat16 g_btcat[(size_t)N_ALL * 128];  // [Bh|Bh|Bl|0]

// ---------------- PTX helpers -------------------------------------------------
__device__ __forceinline__ uint32_t smem_u32(const void* p) {
    uint32_t a;
    asm("{ .reg .u64 t; cvta.to.shared.u64 t, %1; cvt.u32.u64 %0, t; }" : "=r"(a) : "l"(p));
    return a;
}
#define CP_ASYNC16(dst, src) \
    asm volatile("cp.async.cg.shared.global [%0], [%1], 16;" :: "r"((uint32_t)(dst)), "l"(src))
#define CP_ASYNC_COMMIT() asm volatile("cp.async.commit_group;" ::: "memory")
#define CP_ASYNC_WAIT(n)  asm volatile("cp.async.wait_group %0;" :: "n"(n) : "memory")

__device__ __forceinline__ void ldmatrix_x4(uint32_t* r, uint32_t addr) {
    asm volatile("ldmatrix.sync.aligned.m8n8.x4.shared.b16 {%0,%1,%2,%3}, [%4];"
                 : "=r"(r[0]), "=r"(r[1]), "=r"(r[2]), "=r"(r[3]) : "r"(addr));
}
__device__ __forceinline__ void mma_bf16(float* d, const uint32_t* a, uint32_t b0, uint32_t b1) {
    asm volatile(
        "mma.sync.aligned.m16n8k16.row.col.f32.bf16.bf16.f32 "
        "{%0,%1,%2,%3}, {%4,%5,%6,%7}, {%8,%9}, {%0,%1,%2,%3};"
        : "+f"(d[0]), "+f"(d[1]), "+f"(d[2]), "+f"(d[3])
        : "r"(a[0]), "r"(a[1]), "r"(a[2]), "r"(a[3]), "r"(b0), "r"(b1));
}

// ---------------- conversion kernels ------------------------------------------
__device__ __forceinline__ void split1(float v, __nv_bfloat16& h, __nv_bfloat16& l) {
    h = __float2bfloat16(v);
    l = __float2bfloat16(v - __bfloat162float(h));
}
__global__ void __launch_bounds__(256) conv_split_kernel(const float4* __restrict__ src,
                                                         __nv_bfloat16* __restrict__ dhi,
                                                         __nv_bfloat16* __restrict__ dlo) {
    size_t i = (size_t)blockIdx.x * 256 + threadIdx.x;
    float4 v = src[i];
    __nv_bfloat16 h0, h1, h2, h3, l0, l1, l2, l3;
    split1(v.x, h0, l0); split1(v.y, h1, l1); split1(v.z, h2, l2); split1(v.w, h3, l3);
    __nv_bfloat162* hi = reinterpret_cast<__nv_bfloat162*>(dhi);
    __nv_bfloat162* lo = reinterpret_cast<__nv_bfloat162*>(dlo);
    hi[2 * i]     = __halves2bfloat162(h0, h1);
    hi[2 * i + 1] = __halves2bfloat162(h2, h3);
    lo[2 * i]     = __halves2bfloat162(l0, l1);
    lo[2 * i + 1] = __halves2bfloat162(l2, l3);
}

// B is [32, 4096]; g_btcat[n][0:128] = [Bh(:,n) | Bh | Bl | 0]
__global__ void __launch_bounds__(256) conv_b_kernel(const float* __restrict__ Bm) {
    int n = blockIdx.x * 256 + threadIdx.x;
    __nv_bfloat16* row = g_btcat + (size_t)n * 128;
    __nv_bfloat16 z = __float2bfloat16(0.f);
#pragma unroll
    for (int r = 0; r < RNK; ++r) {
        float v = Bm[(size_t)r * N_ALL + n];
        __nv_bfloat16 h, l;
        split1(v, h, l);
        row[r] = h; row[32 + r] = h; row[64 + r] = l; row[96 + r] = z;
    }
}

// T = (x*mask)@A (fp32), then g_tcat[m] = [Th | Tl | Th | 0]
__global__ void __launch_bounds__(256) t_kernel(const float* __restrict__ x,
                                                const float* __restrict__ mask,
                                                const float* __restrict__ A) {
    __shared__ float xm[32 * 132];
    __shared__ float4 a_sm[128 * 8];
    const int tid = threadIdx.x;
    const int m0 = blockIdx.x * 32;
    const int mrow = tid >> 3;
    const int rg = tid & 7;
    float acc0 = 0.f, acc1 = 0.f, acc2 = 0.f, acc3 = 0.f;

    for (int kc = 0; kc < K_ALL; kc += 128) {
        __syncthreads();
#pragma unroll
        for (int i = 0; i < 16; ++i) {
            int idx = tid + i * 256;
            int row = idx >> 7, col = idx & 127;
            size_t g = (size_t)(m0 + row) * K_ALL + kc + col;
            xm[row * 132 + col] = x[g] * mask[g];
        }
        const float4* a4 = reinterpret_cast<const float4*>(A) + (size_t)kc * 8;
#pragma unroll
        for (int i = 0; i < 4; ++i) a_sm[tid + i * 256] = a4[tid + i * 256];
        __syncthreads();
#pragma unroll 4
        for (int k = 0; k < 128; ++k) {
            float xv = xm[mrow * 132 + k];
            float4 av = a_sm[k * 8 + rg];
            acc0 += xv * av.x; acc1 += xv * av.y; acc2 += xv * av.z; acc3 += xv * av.w;
        }
    }
    int m = m0 + mrow, r = rg * 4;
    __nv_bfloat16* row = g_tcat + (size_t)m * 128;
    float vals[4] = {acc0, acc1, acc2, acc3};
    __nv_bfloat16 z = __float2bfloat16(0.f);
#pragma unroll
    for (int j = 0; j < 4; ++j) {
        __nv_bfloat16 h, l;
        split1(vals[j], h, l);
        row[r + j] = h; row[32 + r + j] = l; row[64 + r + j] = h; row[96 + r + j] = z;
    }
}

// ---------------- fused GEMM ---------------------------------------------------
// CTA tile 128(M) x 256(N), 256 threads (8 warps = 2M x 4N, warp tile 64x64).
// 194 K-chunks of 64:
//   [0,64): xh@Wh  [64,128): xl@Wh  [128,192): xh@Wl  [192,194): Tcat@Btcat
#define NCHUNK 194
#define PITCH 72                        // b16 elements per smem row (144 B, padded)
#define A_BYTES (128 * PITCH * 2)       // 18432
#define B_BYTES (256 * PITCH * 2)       // 36864
#define STAGE_BYTES (A_BYTES + B_BYTES) // 55296
#define NSTAGE 3
#define GEMM_SMEM (NSTAGE * STAGE_BYTES)

__device__ __forceinline__ void load_chunk(int c, int stage, int tid, int m0, int n0,
                                           uint32_t smem_base) {
    const __nv_bfloat16 *pa, *pb;
    int lda, ldb, k0;
    if (c < 64)       { pa = g_xhi;  pb = g_whi;   lda = K_ALL; ldb = K_ALL; k0 = c << 6; }
    else if (c < 128) { pa = g_xlo;  pb = g_whi;   lda = K_ALL; ldb = K_ALL; k0 = (c - 64) << 6; }
    else if (c < 192) { pa = g_xhi;  pb = g_wlo;   lda = K_ALL; ldb = K_ALL; k0 = (c - 128) << 6; }
    else              { pa = g_tcat; pb = g_btcat; lda = 128;   ldb = 128;   k0 = (c - 192) << 6; }
    uint32_t sA = smem_base + stage * STAGE_BYTES;
    uint32_t sB = sA + A_BYTES;
#pragma unroll
    for (int i = 0; i < 4; ++i) {                 // A: 128 rows x 8 x 16B
        int op = tid + i * 256;
        int row = op >> 3, col = op & 7;
        const __nv_bfloat16* src = pa + (size_t)(m0 + row) * lda + k0 + col * 8;
        CP_ASYNC16(sA + (uint32_t)(row * 144 + col * 16), src);
    }
#pragma unroll
    for (int i = 0; i < 8; ++i) {                 // B: 256 rows x 8 x 16B
        int op = tid + i * 256;
        int row = op >> 3, col = op & 7;
        const __nv_bfloat16* src = pb + (size_t)(n0 + row) * ldb + k0 + col * 8;
        CP_ASYNC16(sB + (uint32_t)(row * 144 + col * 16), src);
    }
}

__global__ void __launch_bounds__(256, 1)
lora_gemm_kernel(float* __restrict__ out) {
    extern __shared__ __align__(1024) char smem[];
    const uint32_t smem_base = smem_u32(smem);
    const int tid = threadIdx.x;
    const int wid = tid >> 5;
    const int lane = tid & 31;
    // raster swizzle: groups of 8 m-tiles x 16 n-tiles
    const int grp = blockIdx.x >> 7;
    const int rr  = blockIdx.x & 127;
    const int m0 = (grp * 8 + (rr & 7)) * 128;
    const int n0 = (rr >> 3) * 256;
    const int m_w = (wid >> 2) * 64;     // warp M offset in tile
    const int n_w = (wid & 3) * 64;      // warp N offset in tile

    // per-lane ldmatrix base byte offsets (within a stage)
    // A frag f: rows m_w+f*16+(lane&15), col half (lane>>4)*8 (x2 bytes)
    uint32_t aoff[4];
#pragma unroll
    for (int f = 0; f < 4; ++f)
        aoff[f] = (uint32_t)((m_w + f * 16 + (lane & 15)) * 144 + (lane >> 4) * 16);
    // B pair jj: n = n_w + jj*16 + (lane>>4)*8 + (lane&7), k half ((lane>>3)&1)*8
    uint32_t boff[4];
#pragma unroll
    for (int jj = 0; jj < 4; ++jj)
        boff[jj] = (uint32_t)(A_BYTES + (n_w + jj * 16 + ((lane >> 4) << 3) + (lane & 7)) * 144 +
                              ((lane >> 3) & 1) * 16);

    float acc[4][8][4];
#pragma unroll
    for (int f = 0; f < 4; ++f)
#pragma unroll
        for (int j = 0; j < 8; ++j)
#pragma unroll
            for (int v = 0; v < 4; ++v) acc[f][j][v] = 0.f;

    // prologue: chunks 0,1 into stages 0,1
    load_chunk(0, 0, tid, m0, n0, smem_base);
    CP_ASYNC_COMMIT();
    load_chunk(1, 1, tid, m0, n0, smem_base);
    CP_ASYNC_COMMIT();

    int stage = 0;
    for (int c = 0; c < NCHUNK; ++c) {
        CP_ASYNC_WAIT(1);
        __syncthreads();
        const int cl = c + 2;
        if (cl < NCHUNK) {
            int sl = cl % NSTAGE;
            load_chunk(cl, sl, tid, m0, n0, smem_base);
        }
        CP_ASYNC_COMMIT();

        const uint32_t sbase = smem_base + stage * STAGE_BYTES;
#pragma unroll
        for (int ks = 0; ks < 4; ++ks) {
            uint32_t a[4][4], b[4][4];
#pragma unroll
            for (int f = 0; f < 4; ++f) ldmatrix_x4(a[f], sbase + aoff[f] + ks * 32);
#pragma unroll
            for (int jj = 0; jj < 4; ++jj) ldmatrix_x4(b[jj], sbase + boff[jj] + ks * 32);
#pragma unroll
            for (int f = 0; f < 4; ++f)
#pragma unroll
                for (int j = 0; j < 8; ++j)
                    mma_bf16(acc[f][j], a[f], b[j >> 1][(j & 1) * 2], b[j >> 1][(j & 1) * 2 + 1]);
        }
        __syncthreads();
        stage = (stage + 1 == NSTAGE) ? 0 : stage + 1;
    }

    // epilogue: direct fp32 stores
    const int g8 = lane >> 2;      // 0..7
    const int t4 = lane & 3;       // 0..3
#pragma unroll
    for (int f = 0; f < 4; ++f) {
        const int mrow = m0 + m_w + f * 16 + g8;
#pragma unroll
        for (int j = 0; j < 8; ++j) {
            const int ncol = n0 + n_w + j * 8 + t4 * 2;
            float2 v0 = make_float2(acc[f][j][0], acc[f][j][1]);
            float2 v1 = make_float2(acc[f][j][2], acc[f][j][3]);
            *reinterpret_cast<float2*>(out + (size_t)mrow * N_ALL + ncol) = v0;
            *reinterpret_cast<float2*>(out + (size_t)(mrow + 8) * N_ALL + ncol) = v1;
        }
    }
}

// ---------------- launch ---------------------------------------------------------
extern "C" void kernel_launch(void* const* d_in, const int* in_sizes, int n_in,
                              void* d_out, int out_size) {
    const float* x    = (const float*)d_in[0];   // [8192, 4096]
    const float* W    = (const float*)d_in[1];   // [4096, 4096]
    const float* A    = (const float*)d_in[2];   // [4096, 32]
    const float* Bm   = (const float*)d_in[3];   // [32, 4096]
    const float* mask = (const float*)d_in[4];   // [8192, 4096]
    float* out = (float*)d_out;

    __nv_bfloat16 *xhi, *xlo, *whi, *wlo;
    cudaGetSymbolAddress((void**)&xhi, g_xhi);
    cudaGetSymbolAddress((void**)&xlo, g_xlo);
    cudaGetSymbolAddress((void**)&whi, g_whi);
    cudaGetSymbolAddress((void**)&wlo, g_wlo);

    static bool attr_set = false;
    if (!attr_set) {
        cudaFuncSetAttribute(lora_gemm_kernel,
                             cudaFuncAttributeMaxDynamicSharedMemorySize, GEMM_SMEM);
        attr_set = true;
    }

    conv_split_kernel<<<32768, 256>>>((const float4*)x, xhi, xlo);
    conv_split_kernel<<<16384, 256>>>((const float4*)W, whi, wlo);
    conv_b_kernel<<<16, 256>>>(Bm);
    t_kernel<<<256, 256>>>(x, mask, A);
    lora_gemm_kernel<<<1024, 256, GEMM_SMEM>>>(out);
}

// round 4
// speedup vs baseline: 1.0129x; 1.0129x over previous
#include <cuda_runtime.h>
#include <cuda_bf16.h>
#include <cstdint>

// out[8192,4096] = x@W^T + ((x*mask)@A)@B   (fp32, SCALE=1)
#define M_ALL 8192
#define N_ALL 4096
#define K_ALL 4096
#define RNK   32
#define TSLICES 4

// ---------------- scratch (__device__ globals; no allocs allowed) ------------
__device__ __align__(256) __nv_bfloat16 g_xhi[(size_t)M_ALL * K_ALL];
__device__ __align__(256) __nv_bfloat16 g_xlo[(size_t)M_ALL * K_ALL];
__device__ __align__(256) __nv_bfloat16 g_whi[(size_t)N_ALL * K_ALL];
__device__ __align__(256) __nv_bfloat16 g_wlo[(size_t)N_ALL * K_ALL];
__device__ __align__(256) __nv_bfloat16 g_tcat[(size_t)M_ALL * 128];   // [Th|Tl|Th|0]
__device__ __align__(256) __nv_bfloat16 g_btcat[(size_t)N_ALL * 128];  // [Bh|Bh|Bl|0]
__device__ __align__(256) float g_tpart[TSLICES][M_ALL][RNK];          // 4 MB partials

// ---------------- PTX helpers -------------------------------------------------
__device__ __forceinline__ uint32_t smem_u32(const void* p) {
    uint32_t a;
    asm("{ .reg .u64 t; cvta.to.shared.u64 t, %1; cvt.u32.u64 %0, t; }" : "=r"(a) : "l"(p));
    return a;
}
#define CP_ASYNC16(dst, src) \
    asm volatile("cp.async.cg.shared.global [%0], [%1], 16;" :: "r"((uint32_t)(dst)), "l"(src))
#define CP_ASYNC_COMMIT() asm volatile("cp.async.commit_group;" ::: "memory")
#define CP_ASYNC_WAIT(n)  asm volatile("cp.async.wait_group %0;" :: "n"(n) : "memory")

__device__ __forceinline__ void ldmatrix_x4(uint32_t* r, uint32_t addr) {
    asm volatile("ldmatrix.sync.aligned.m8n8.x4.shared.b16 {%0,%1,%2,%3}, [%4];"
                 : "=r"(r[0]), "=r"(r[1]), "=r"(r[2]), "=r"(r[3]) : "r"(addr));
}
__device__ __forceinline__ void mma_bf16(float* d, const uint32_t* a, uint32_t b0, uint32_t b1) {
    asm volatile(
        "mma.sync.aligned.m16n8k16.row.col.f32.bf16.bf16.f32 "
        "{%0,%1,%2,%3}, {%4,%5,%6,%7}, {%8,%9}, {%0,%1,%2,%3};"
        : "+f"(d[0]), "+f"(d[1]), "+f"(d[2]), "+f"(d[3])
        : "r"(a[0]), "r"(a[1]), "r"(a[2]), "r"(a[3]), "r"(b0), "r"(b1));
}

// ---------------- conversion kernels ------------------------------------------
__device__ __forceinline__ void split1(float v, __nv_bfloat16& h, __nv_bfloat16& l) {
    h = __float2bfloat16(v);
    l = __float2bfloat16(v - __bfloat162float(h));
}
__global__ void __launch_bounds__(256) conv_split_kernel(const float4* __restrict__ src,
                                                         __nv_bfloat16* __restrict__ dhi,
                                                         __nv_bfloat16* __restrict__ dlo) {
    size_t i = (size_t)blockIdx.x * 256 + threadIdx.x;
    float4 v = src[i];
    __nv_bfloat16 h0, h1, h2, h3, l0, l1, l2, l3;
    split1(v.x, h0, l0); split1(v.y, h1, l1); split1(v.z, h2, l2); split1(v.w, h3, l3);
    __nv_bfloat162* hi = reinterpret_cast<__nv_bfloat162*>(dhi);
    __nv_bfloat162* lo = reinterpret_cast<__nv_bfloat162*>(dlo);
    hi[2 * i]     = __halves2bfloat162(h0, h1);
    hi[2 * i + 1] = __halves2bfloat162(h2, h3);
    lo[2 * i]     = __halves2bfloat162(l0, l1);
    lo[2 * i + 1] = __halves2bfloat162(l2, l3);
}

// B is [32, 4096]; g_btcat[n][0:128] = [Bh(:,n) | Bh | Bl | 0]
__global__ void __launch_bounds__(256) conv_b_kernel(const float* __restrict__ Bm) {
    int n = blockIdx.x * 256 + threadIdx.x;
    __nv_bfloat16* row = g_btcat + (size_t)n * 128;
    __nv_bfloat16 z = __float2bfloat16(0.f);
#pragma unroll
    for (int r = 0; r < RNK; ++r) {
        float v = Bm[(size_t)r * N_ALL + n];
        __nv_bfloat16 h, l;
        split1(v, h, l);
        row[r] = h; row[32 + r] = h; row[64 + r] = l; row[96 + r] = z;
    }
}

// ---- T path: partial sums over K-slices (grid 256 x TSLICES), float4 loads ----
__global__ void __launch_bounds__(256) t_partial_kernel(const float* __restrict__ x,
                                                        const float* __restrict__ mask,
                                                        const float* __restrict__ A) {
    __shared__ float xm[32 * 132];
    __shared__ float4 a_sm[128 * 8];
    const int tid = threadIdx.x;
    const int m0 = blockIdx.x * 32;
    const int slice = blockIdx.y;
    const int kbase = slice * (K_ALL / TSLICES);
    const int mrow = tid >> 3;
    const int rg = tid & 7;
    float acc0 = 0.f, acc1 = 0.f, acc2 = 0.f, acc3 = 0.f;

    const float4* x4 = reinterpret_cast<const float4*>(x);
    const float4* m4 = reinterpret_cast<const float4*>(mask);

    for (int kc = 0; kc < K_ALL / TSLICES; kc += 128) {
        __syncthreads();
#pragma unroll
        for (int i = 0; i < 4; ++i) {                 // 1024 float4: 32 rows x 32 f4
            int idx = tid + i * 256;
            int row = idx >> 5, c4 = idx & 31;
            size_t g = ((size_t)(m0 + row) * K_ALL + kbase + kc) / 4 + c4;
            float4 xv = x4[g];
            float4 mv = m4[g];
            float* dst = &xm[row * 132 + c4 * 4];
            dst[0] = xv.x * mv.x; dst[1] = xv.y * mv.y;
            dst[2] = xv.z * mv.z; dst[3] = xv.w * mv.w;
        }
        const float4* a4 = reinterpret_cast<const float4*>(A) + (size_t)(kbase + kc) * 8;
#pragma unroll
        for (int i = 0; i < 4; ++i) a_sm[tid + i * 256] = a4[tid + i * 256];
        __syncthreads();
#pragma unroll 4
        for (int k = 0; k < 128; ++k) {
            float xv = xm[mrow * 132 + k];
            float4 av = a_sm[k * 8 + rg];
            acc0 += xv * av.x; acc1 += xv * av.y; acc2 += xv * av.z; acc3 += xv * av.w;
        }
    }
    float* dst = &g_tpart[slice][m0 + mrow][rg * 4];
    dst[0] = acc0; dst[1] = acc1; dst[2] = acc2; dst[3] = acc3;
}

// sum partials, split, pack g_tcat[m] = [Th | Tl | Th | 0]
__global__ void __launch_bounds__(256) t_pack_kernel() {
    int idx = blockIdx.x * 256 + threadIdx.x;      // 65536 = 8192 m x 8 rgroups
    int m = idx >> 3, rg = idx & 7, r = rg * 4;
    float v[4];
#pragma unroll
    for (int j = 0; j < 4; ++j) {
        float s = 0.f;
#pragma unroll
        for (int sl = 0; sl < TSLICES; ++sl) s += g_tpart[sl][m][r + j];
        v[j] = s;
    }
    __nv_bfloat16* row = g_tcat + (size_t)m * 128;
    __nv_bfloat16 z = __float2bfloat16(0.f);
#pragma unroll
    for (int j = 0; j < 4; ++j) {
        __nv_bfloat16 h, l;
        split1(v[j], h, l);
        row[r + j] = h; row[32 + r + j] = l; row[64 + r + j] = h; row[96 + r + j] = z;
    }
}

// ---------------- fused GEMM ---------------------------------------------------
// CTA tile 128(M) x 256(N), 256 threads (8 warps = 2M x 4N, warp tile 64x64).
// 194 K-chunks of 64:
//   [0,64): xh@Wh  [64,128): xl@Wh  [128,192): xh@Wl  [192,194): Tcat@Btcat
// 4-stage cp.async pipeline, ONE __syncthreads per chunk.
#define NCHUNK 194
#define PITCH 72                        // b16 per smem row (144 B, padded)
#define A_BYTES (128 * PITCH * 2)       // 18432
#define B_BYTES (256 * PITCH * 2)       // 36864
#define STAGE_BYTES (A_BYTES + B_BYTES) // 55296
#define NSTAGE 4
#define GEMM_SMEM (NSTAGE * STAGE_BYTES) // 221184

__device__ __forceinline__ void load_chunk(int c, int stage, int tid, int m0, int n0,
                                           uint32_t smem_base) {
    const __nv_bfloat16 *pa, *pb;
    int lda, ldb, k0;
    if (c < 64)       { pa = g_xhi;  pb = g_whi;   lda = K_ALL; ldb = K_ALL; k0 = c << 6; }
    else if (c < 128) { pa = g_xlo;  pb = g_whi;   lda = K_ALL; ldb = K_ALL; k0 = (c - 64) << 6; }
    else if (c < 192) { pa = g_xhi;  pb = g_wlo;   lda = K_ALL; ldb = K_ALL; k0 = (c - 128) << 6; }
    else              { pa = g_tcat; pb = g_btcat; lda = 128;   ldb = 128;   k0 = (c - 192) << 6; }
    uint32_t sA = smem_base + stage * STAGE_BYTES;
    uint32_t sB = sA + A_BYTES;
#pragma unroll
    for (int i = 0; i < 4; ++i) {                 // A: 128 rows x 8 x 16B
        int op = tid + i * 256;
        int row = op >> 3, col = op & 7;
        const __nv_bfloat16* src = pa + (size_t)(m0 + row) * lda + k0 + col * 8;
        CP_ASYNC16(sA + (uint32_t)(row * 144 + col * 16), src);
    }
#pragma unroll
    for (int i = 0; i < 8; ++i) {                 // B: 256 rows x 8 x 16B
        int op = tid + i * 256;
        int row = op >> 3, col = op & 7;
        const __nv_bfloat16* src = pb + (size_t)(n0 + row) * ldb + k0 + col * 8;
        CP_ASYNC16(sB + (uint32_t)(row * 144 + col * 16), src);
    }
}

__global__ void __launch_bounds__(256, 1)
lora_gemm_kernel(float* __restrict__ out) {
    extern __shared__ __align__(1024) char smem[];
    const uint32_t smem_base = smem_u32(smem);
    const int tid = threadIdx.x;
    const int wid = tid >> 5;
    const int lane = tid & 31;
    // raster swizzle: groups of 8 m-tiles x 16 n-tiles
    const int grp = blockIdx.x >> 7;
    const int rr  = blockIdx.x & 127;
    const int m0 = (grp * 8 + (rr & 7)) * 128;
    const int n0 = (rr >> 3) * 256;
    const int m_w = (wid >> 2) * 64;
    const int n_w = (wid & 3) * 64;

    uint32_t aoff[4];
#pragma unroll
    for (int f = 0; f < 4; ++f)
        aoff[f] = (uint32_t)((m_w + f * 16 + (lane & 15)) * 144 + (lane >> 4) * 16);
    uint32_t boff[4];
#pragma unroll
    for (int jj = 0; jj < 4; ++jj)
        boff[jj] = (uint32_t)(A_BYTES + (n_w + jj * 16 + ((lane >> 4) << 3) + (lane & 7)) * 144 +
                              ((lane >> 3) & 1) * 16);

    float acc[4][8][4];
#pragma unroll
    for (int f = 0; f < 4; ++f)
#pragma unroll
        for (int j = 0; j < 8; ++j)
#pragma unroll
            for (int v = 0; v < 4; ++v) acc[f][j][v] = 0.f;

    // prologue: chunks 0..2 into stages 0..2
#pragma unroll
    for (int c = 0; c < NSTAGE - 1; ++c) {
        load_chunk(c, c, tid, m0, n0, smem_base);
        CP_ASYNC_COMMIT();
    }

    for (int c = 0; c < NCHUNK; ++c) {
        CP_ASYNC_WAIT(NSTAGE - 2);       // chunk c resident
        __syncthreads();                 // single barrier per chunk
        const int cl = c + NSTAGE - 1;
        if (cl < NCHUNK) load_chunk(cl, cl & (NSTAGE - 1), tid, m0, n0, smem_base);
        CP_ASYNC_COMMIT();

        const uint32_t sbase = smem_base + (c & (NSTAGE - 1)) * STAGE_BYTES;
#pragma unroll
        for (int ks = 0; ks < 4; ++ks) {
            uint32_t a[4][4], b[4][4];
#pragma unroll
            for (int f = 0; f < 4; ++f) ldmatrix_x4(a[f], sbase + aoff[f] + ks * 32);
#pragma unroll
            for (int jj = 0; jj < 4; ++jj) ldmatrix_x4(b[jj], sbase + boff[jj] + ks * 32);
#pragma unroll
            for (int f = 0; f < 4; ++f)
#pragma unroll
                for (int j = 0; j < 8; ++j)
                    mma_bf16(acc[f][j], a[f], b[j >> 1][(j & 1) * 2], b[j >> 1][(j & 1) * 2 + 1]);
        }
    }

    // epilogue: direct fp32 stores
    const int g8 = lane >> 2;
    const int t4 = lane & 3;
#pragma unroll
    for (int f = 0; f < 4; ++f) {
        const int mrow = m0 + m_w + f * 16 + g8;
#pragma unroll
        for (int j = 0; j < 8; ++j) {
            const int ncol = n0 + n_w + j * 8 + t4 * 2;
            float2 v0 = make_float2(acc[f][j][0], acc[f][j][1]);
            float2 v1 = make_float2(acc[f][j][2], acc[f][j][3]);
            *reinterpret_cast<float2*>(out + (size_t)mrow * N_ALL + ncol) = v0;
            *reinterpret_cast<float2*>(out + (size_t)(mrow + 8) * N_ALL + ncol) = v1;
        }
    }
}

// ---------------- launch ---------------------------------------------------------
extern "C" void kernel_launch(void* const* d_in, const int* in_sizes, int n_in,
                              void* d_out, int out_size) {
    const float* x    = (const float*)d_in[0];   // [8192, 4096]
    const float* W    = (const float*)d_in[1];   // [4096, 4096]
    const float* A    = (const float*)d_in[2];   // [4096, 32]
    const float* Bm   = (const float*)d_in[3];   // [32, 4096]
    const float* mask = (const float*)d_in[4];   // [8192, 4096]
    float* out = (float*)d_out;

    __nv_bfloat16 *xhi, *xlo, *whi, *wlo;
    cudaGetSymbolAddress((void**)&xhi, g_xhi);
    cudaGetSymbolAddress((void**)&xlo, g_xlo);
    cudaGetSymbolAddress((void**)&whi, g_whi);
    cudaGetSymbolAddress((void**)&wlo, g_wlo);

    static bool attr_set = false;
    if (!attr_set) {
        cudaFuncSetAttribute(lora_gemm_kernel,
                             cudaFuncAttributeMaxDynamicSharedMemorySize, GEMM_SMEM);
        attr_set = true;
    }

    conv_split_kernel<<<32768, 256>>>((const float4*)x, xhi, xlo);
    conv_split_kernel<<<16384, 256>>>((const float4*)W, whi, wlo);
    conv_b_kernel<<<16, 256>>>(Bm);
    t_partial_kernel<<<dim3(256, TSLICES), 256>>>(x, mask, A);
    t_pack_kernel<<<256, 256>>>();
    lora_gemm_kernel<<<1024, 256, GEMM_SMEM>>>(out);
}

// round 6
// speedup vs baseline: 1.1634x; 1.1486x over previous
#include <cuda_runtime.h>
#include <cuda_bf16.h>
#include <cstdint>

// out[8192,4096] = x@W^T + ((x*mask)@A)@B   (fp32, SCALE=1)
#define M_ALL 8192
#define N_ALL 4096
#define K_ALL 4096
#define RNK   32
#define TSLICES 4

// ---------------- scratch (__device__ globals; no allocs allowed) ------------
__device__ __align__(256) __nv_bfloat16 g_xhi[(size_t)M_ALL * K_ALL];
__device__ __align__(256) __nv_bfloat16 g_xlo[(size_t)M_ALL * K_ALL];
__device__ __align__(256) __nv_bfloat16 g_whi[(size_t)N_ALL * K_ALL];
__device__ __align__(256) __nv_bfloat16 g_wlo[(size_t)N_ALL * K_ALL];
__device__ __align__(256) __nv_bfloat16 g_tcat[(size_t)M_ALL * 128];   // [Th|Tl|Th|0]
__device__ __align__(256) __nv_bfloat16 g_btcat[(size_t)N_ALL * 128];  // [Bh|Bh|Bl|0]
__device__ __align__(256) float g_tpart[TSLICES][M_ALL][RNK];

// ---------------- PTX helpers -------------------------------------------------
__device__ __forceinline__ uint32_t smem_u32(const void* p) {
    uint32_t a;
    asm("{ .reg .u64 t; cvta.to.shared.u64 t, %1; cvt.u32.u64 %0, t; }" : "=r"(a) : "l"(p));
    return a;
}
#define CP_ASYNC16(dst, src) \
    asm volatile("cp.async.cg.shared.global [%0], [%1], 16;" :: "r"((uint32_t)(dst)), "l"(src))
#define CP_ASYNC_COMMIT() asm volatile("cp.async.commit_group;" ::: "memory")
#define CP_ASYNC_WAIT(n)  asm volatile("cp.async.wait_group %0;" :: "n"(n) : "memory")

__device__ __forceinline__ void ldmatrix_x4(uint32_t* r, uint32_t addr) {
    asm volatile("ldmatrix.sync.aligned.m8n8.x4.shared.b16 {%0,%1,%2,%3}, [%4];"
                 : "=r"(r[0]), "=r"(r[1]), "=r"(r[2]), "=r"(r[3]) : "r"(addr));
}
__device__ __forceinline__ void mma_bf16(float* d, const uint32_t* a, uint32_t b0, uint32_t b1) {
    asm volatile(
        "mma.sync.aligned.m16n8k16.row.col.f32.bf16.bf16.f32 "
        "{%0,%1,%2,%3}, {%4,%5,%6,%7}, {%8,%9}, {%0,%1,%2,%3};"
        : "+f"(d[0]), "+f"(d[1]), "+f"(d[2]), "+f"(d[3])
        : "r"(a[0]), "r"(a[1]), "r"(a[2]), "r"(a[3]), "r"(b0), "r"(b1));
}

// ---------------- helpers ------------------------------------------------------
__device__ __forceinline__ void split1(float v, __nv_bfloat16& h, __nv_bfloat16& l) {
    h = __float2bfloat16(v);
    l = __float2bfloat16(v - __bfloat162float(h));
}
__device__ __forceinline__ void conv_body(const float4* __restrict__ src, size_t i,
                                          __nv_bfloat16* __restrict__ dhi,
                                          __nv_bfloat16* __restrict__ dlo) {
    float4 v = src[i];
    __nv_bfloat16 h0, h1, h2, h3, l0, l1, l2, l3;
    split1(v.x, h0, l0); split1(v.y, h1, l1); split1(v.z, h2, l2); split1(v.w, h3, l3);
    __nv_bfloat162* hi = reinterpret_cast<__nv_bfloat162*>(dhi);
    __nv_bfloat162* lo = reinterpret_cast<__nv_bfloat162*>(dlo);
    hi[2 * i]     = __halves2bfloat162(h0, h1);
    hi[2 * i + 1] = __halves2bfloat162(h2, h3);
    lo[2 * i]     = __halves2bfloat162(l0, l1);
    lo[2 * i + 1] = __halves2bfloat162(l2, l3);
}

// kernel #2: convert x
__global__ void __launch_bounds__(256) conv_x_kernel(const float4* __restrict__ x) {
    conv_body(x, (size_t)blockIdx.x * 256 + threadIdx.x, g_xhi, g_xlo);
}

// kernel #1: T partials. Block = 64 m-rows, K-slice 1024. Thread: 2 m-rows x 4 r.
// DYNAMIC smem (50176 B > 48KB static limit): xm[64*132] floats + a_sm[128*8] float4.
#define T_XM_ELEMS (64 * 132)
#define T_SMEM_BYTES (T_XM_ELEMS * 4 + 128 * 8 * 16)   // 33792 + 16384 = 50176
__global__ void __launch_bounds__(256) t_partial_kernel(const float* __restrict__ x,
                                                        const float* __restrict__ mask,
                                                        const float* __restrict__ A) {
    extern __shared__ __align__(16) char tsm[];
    float* xm = reinterpret_cast<float*>(tsm);
    float4* a_sm = reinterpret_cast<float4*>(tsm + T_XM_ELEMS * 4);
    const int tid = threadIdx.x;
    const int m0 = blockIdx.x * 64;
    const int slice = blockIdx.y;
    const int kbase = slice * (K_ALL / TSLICES);
    const int mq = tid >> 3;          // 0..31 -> rows 2*mq, 2*mq+1
    const int rg = tid & 7;           // 0..7  -> r = rg*4
    float acc[2][4];
#pragma unroll
    for (int u = 0; u < 2; ++u)
#pragma unroll
        for (int j = 0; j < 4; ++j) acc[u][j] = 0.f;

    const float4* x4 = reinterpret_cast<const float4*>(x);
    const float4* m4 = reinterpret_cast<const float4*>(mask);

    for (int kc = 0; kc < K_ALL / TSLICES; kc += 128) {
        __syncthreads();
#pragma unroll
        for (int i = 0; i < 8; ++i) {             // 2048 float4: 64 rows x 32 f4
            int idx = tid + i * 256;
            int row = idx >> 5, c4 = idx & 31;
            size_t g = ((size_t)(m0 + row) * K_ALL + kbase + kc) / 4 + c4;
            float4 xv = x4[g];
            float4 mv = m4[g];
            float* dst = &xm[row * 132 + c4 * 4];
            dst[0] = xv.x * mv.x; dst[1] = xv.y * mv.y;
            dst[2] = xv.z * mv.z; dst[3] = xv.w * mv.w;
        }
        const float4* a4 = reinterpret_cast<const float4*>(A) + (size_t)(kbase + kc) * 8;
#pragma unroll
        for (int i = 0; i < 4; ++i) a_sm[tid + i * 256] = a4[tid + i * 256];
        __syncthreads();
#pragma unroll 4
        for (int k = 0; k < 128; ++k) {
            float4 av = a_sm[k * 8 + rg];
            float x0 = xm[(mq * 2) * 132 + k];
            float x1 = xm[(mq * 2 + 1) * 132 + k];
            acc[0][0] += x0 * av.x; acc[0][1] += x0 * av.y;
            acc[0][2] += x0 * av.z; acc[0][3] += x0 * av.w;
            acc[1][0] += x1 * av.x; acc[1][1] += x1 * av.y;
            acc[1][2] += x1 * av.z; acc[1][3] += x1 * av.w;
        }
    }
#pragma unroll
    for (int u = 0; u < 2; ++u) {
        float* dst = &g_tpart[slice][m0 + mq * 2 + u][rg * 4];
        dst[0] = acc[u][0]; dst[1] = acc[u][1]; dst[2] = acc[u][2]; dst[3] = acc[u][3];
    }
}

// kernel #3 (fused): conv W (16384 blocks) + conv B (16 blocks) + t_pack (256 blocks)
__global__ void __launch_bounds__(256) fused_prep_kernel(const float4* __restrict__ W,
                                                         const float* __restrict__ Bm) {
    const int b = blockIdx.x;
    const int tid = threadIdx.x;
    if (b < 16384) {
        conv_body(W, (size_t)b * 256 + tid, g_whi, g_wlo);
    } else if (b < 16400) {
        int n = (b - 16384) * 256 + tid;
        __nv_bfloat16* row = g_btcat + (size_t)n * 128;
        __nv_bfloat16 z = __float2bfloat16(0.f);
#pragma unroll
        for (int r = 0; r < RNK; ++r) {
            float v = Bm[(size_t)r * N_ALL + n];
            __nv_bfloat16 h, l;
            split1(v, h, l);
            row[r] = h; row[32 + r] = h; row[64 + r] = l; row[96 + r] = z;
        }
    } else {
        int idx = (b - 16400) * 256 + tid;       // 65536 = 8192 m x 8 rgroups
        int m = idx >> 3, rg = idx & 7, r = rg * 4;
        __nv_bfloat16* row = g_tcat + (size_t)m * 128;
        __nv_bfloat16 z = __float2bfloat16(0.f);
#pragma unroll
        for (int j = 0; j < 4; ++j) {
            float s = 0.f;
#pragma unroll
            for (int sl = 0; sl < TSLICES; ++sl) s += g_tpart[sl][m][r + j];
            __nv_bfloat16 h, l;
            split1(s, h, l);
            row[r + j] = h; row[32 + r + j] = l; row[64 + r + j] = h; row[96 + r + j] = z;
        }
    }
}

// ---------------- fused GEMM ---------------------------------------------------
// CTA tile 128(M) x 128(N), 256 threads (8 warps = 2M x 4N, warp tile 64x32).
// 2 CTAs/SM. 194 K-chunks of 64:
//   [0,64): xh@Wh  [64,128): xl@Wh  [128,192): xh@Wl  [192,194): Tcat@Btcat
#define NCHUNK 194
#define PITCH_B 144                      // bytes per smem row (padded)
#define A_BYTES (128 * PITCH_B)          // 18432
#define B_BYTES (128 * PITCH_B)          // 18432
#define STAGE_BYTES (A_BYTES + B_BYTES)  // 36864
#define NSTAGE 3
#define GEMM_SMEM (NSTAGE * STAGE_BYTES) // 110592

__device__ __forceinline__ void load_chunk(int c, int stage, int tid, int m0, int n0,
                                           uint32_t smem_base) {
    const __nv_bfloat16 *pa, *pb;
    int lda, ldb, k0;
    if (c < 64)       { pa = g_xhi;  pb = g_whi;   lda = K_ALL; ldb = K_ALL; k0 = c << 6; }
    else if (c < 128) { pa = g_xlo;  pb = g_whi;   lda = K_ALL; ldb = K_ALL; k0 = (c - 64) << 6; }
    else if (c < 192) { pa = g_xhi;  pb = g_wlo;   lda = K_ALL; ldb = K_ALL; k0 = (c - 128) << 6; }
    else              { pa = g_tcat; pb = g_btcat; lda = 128;   ldb = 128;   k0 = (c - 192) << 6; }
    uint32_t sA = smem_base + stage * STAGE_BYTES;
    uint32_t sB = sA + A_BYTES;
#pragma unroll
    for (int i = 0; i < 4; ++i) {                 // A: 128 rows x 8 x 16B
        int op = tid + i * 256;
        int row = op >> 3, col = op & 7;
        const __nv_bfloat16* src = pa + (size_t)(m0 + row) * lda + k0 + col * 8;
        CP_ASYNC16(sA + (uint32_t)(row * PITCH_B + col * 16), src);
    }
#pragma unroll
    for (int i = 0; i < 4; ++i) {                 // B: 128 rows x 8 x 16B
        int op = tid + i * 256;
        int row = op >> 3, col = op & 7;
        const __nv_bfloat16* src = pb + (size_t)(n0 + row) * ldb + k0 + col * 8;
        CP_ASYNC16(sB + (uint32_t)(row * PITCH_B + col * 16), src);
    }
}

// kernel #4: the GEMM
__global__ void __launch_bounds__(256, 2)
lora_gemm_kernel(float* __restrict__ out) {
    extern __shared__ __align__(1024) char smem[];
    const uint32_t smem_base = smem_u32(smem);
    const int tid = threadIdx.x;
    const int wid = tid >> 5;
    const int lane = tid & 31;
    // raster: groups of 16 m-tiles x 32 n-tiles (512 CTAs/group)
    const int gid = blockIdx.x >> 9;
    const int rr  = blockIdx.x & 511;
    const int m0 = (gid * 16 + (rr & 15)) * 128;
    const int n0 = (rr >> 4) * 128;
    const int m_w = (wid >> 2) * 64;     // 2 m-warps
    const int n_w = (wid & 3) * 32;      // 4 n-warps

    uint32_t aoff[4];
#pragma unroll
    for (int f = 0; f < 4; ++f)
        aoff[f] = (uint32_t)((m_w + f * 16 + (lane & 15)) * PITCH_B + (lane >> 4) * 16);
    uint32_t boff[2];
#pragma unroll
    for (int jj = 0; jj < 2; ++jj)
        boff[jj] = (uint32_t)(A_BYTES +
                              (n_w + jj * 16 + ((lane >> 4) << 3) + (lane & 7)) * PITCH_B +
                              ((lane >> 3) & 1) * 16);

    float acc[4][4][4];
#pragma unroll
    for (int f = 0; f < 4; ++f)
#pragma unroll
        for (int j = 0; j < 4; ++j)
#pragma unroll
            for (int v = 0; v < 4; ++v) acc[f][j][v] = 0.f;

    // prologue: chunks 0,1 -> stages 0,1
    load_chunk(0, 0, tid, m0, n0, smem_base);
    CP_ASYNC_COMMIT();
    load_chunk(1, 1, tid, m0, n0, smem_base);
    CP_ASYNC_COMMIT();

    int st_c = 0, st_l = 2;
    for (int c = 0; c < NCHUNK; ++c) {
        CP_ASYNC_WAIT(1);                 // chunk c resident
        __syncthreads();
        const int cl = c + 2;
        if (cl < NCHUNK) load_chunk(cl, st_l, tid, m0, n0, smem_base);
        CP_ASYNC_COMMIT();

        const uint32_t sbase = smem_base + st_c * STAGE_BYTES;
#pragma unroll
        for (int ks = 0; ks < 4; ++ks) {
            uint32_t a[4][4], b[2][4];
#pragma unroll
            for (int f = 0; f < 4; ++f) ldmatrix_x4(a[f], sbase + aoff[f] + ks * 32);
#pragma unroll
            for (int jj = 0; jj < 2; ++jj) ldmatrix_x4(b[jj], sbase + boff[jj] + ks * 32);
#pragma unroll
            for (int f = 0; f < 4; ++f)
#pragma unroll
                for (int j = 0; j < 4; ++j)
                    mma_bf16(acc[f][j], a[f], b[j >> 1][(j & 1) * 2], b[j >> 1][(j & 1) * 2 + 1]);
        }
        st_c = (st_c + 1 == NSTAGE) ? 0 : st_c + 1;
        st_l = (st_l + 1 == NSTAGE) ? 0 : st_l + 1;
    }

    // epilogue
    const int g8 = lane >> 2;
    const int t4 = lane & 3;
#pragma unroll
    for (int f = 0; f < 4; ++f) {
        const int mrow = m0 + m_w + f * 16 + g8;
#pragma unroll
        for (int j = 0; j < 4; ++j) {
            const int ncol = n0 + n_w + j * 8 + t4 * 2;
            float2 v0 = make_float2(acc[f][j][0], acc[f][j][1]);
            float2 v1 = make_float2(acc[f][j][2], acc[f][j][3]);
            *reinterpret_cast<float2*>(out + (size_t)mrow * N_ALL + ncol) = v0;
            *reinterpret_cast<float2*>(out + (size_t)(mrow + 8) * N_ALL + ncol) = v1;
        }
    }
}

// ---------------- launch ---------------------------------------------------------
extern "C" void kernel_launch(void* const* d_in, const int* in_sizes, int n_in,
                              void* d_out, int out_size) {
    const float* x    = (const float*)d_in[0];   // [8192, 4096]
    const float* W    = (const float*)d_in[1];   // [4096, 4096]
    const float* A    = (const float*)d_in[2];   // [4096, 32]
    const float* Bm   = (const float*)d_in[3];   // [32, 4096]
    const float* mask = (const float*)d_in[4];   // [8192, 4096]
    float* out = (float*)d_out;

    static bool attr_set = false;
    if (!attr_set) {
        cudaFuncSetAttribute(lora_gemm_kernel,
                             cudaFuncAttributeMaxDynamicSharedMemorySize, GEMM_SMEM);
        cudaFuncSetAttribute(t_partial_kernel,
                             cudaFuncAttributeMaxDynamicSharedMemorySize, T_SMEM_BYTES);
        attr_set = true;
    }

    // launch order chosen so the GEMM is the 4th launch (profiler capture slot)
    t_partial_kernel<<<dim3(128, TSLICES), 256, T_SMEM_BYTES>>>(x, mask, A);
    conv_x_kernel<<<32768, 256>>>((const float4*)x);
    fused_prep_kernel<<<16656, 256>>>((const float4*)W, Bm);
    lora_gemm_kernel<<<2048, 256, GEMM_SMEM>>>(out);
}

// round 7
// speedup vs baseline: 1.6889x; 1.4517x over previous
#include <cuda_runtime.h>
#include <cuda_fp16.h>
#include <cstdint>

// out[8192,4096] = x@W^T + ((x*mask)@A)@B   (fp32, SCALE=1)
// fp16x2 scheme: x = xh + xl (fp16 pair, exact to 2^-22), W ~ fp16 (sole error source)
#define M_ALL 8192
#define N_ALL 4096
#define K_ALL 4096
#define RNK   32
#define TSLICES 4

// ---------------- scratch (__device__ globals; no allocs allowed) ------------
__device__ __align__(256) __half g_xhi[(size_t)M_ALL * K_ALL];
__device__ __align__(256) __half g_xlo[(size_t)M_ALL * K_ALL];
__device__ __align__(256) __half g_whi[(size_t)N_ALL * K_ALL];
__device__ __align__(256) __half g_tcat[(size_t)M_ALL * 64];    // [Th|Tl]
__device__ __align__(256) __half g_btcat[(size_t)N_ALL * 64];   // [Bh|Bh]
__device__ __align__(256) float g_tpart[TSLICES][M_ALL][RNK];

// ---------------- PTX helpers -------------------------------------------------
__device__ __forceinline__ uint32_t smem_u32(const void* p) {
    uint32_t a;
    asm("{ .reg .u64 t; cvta.to.shared.u64 t, %1; cvt.u32.u64 %0, t; }" : "=r"(a) : "l"(p));
    return a;
}
#define CP_ASYNC16(dst, src) \
    asm volatile("cp.async.cg.shared.global [%0], [%1], 16;" :: "r"((uint32_t)(dst)), "l"(src))
#define CP_ASYNC_COMMIT() asm volatile("cp.async.commit_group;" ::: "memory")
#define CP_ASYNC_WAIT(n)  asm volatile("cp.async.wait_group %0;" :: "n"(n) : "memory")

__device__ __forceinline__ void ldmatrix_x4(uint32_t* r, uint32_t addr) {
    asm volatile("ldmatrix.sync.aligned.m8n8.x4.shared.b16 {%0,%1,%2,%3}, [%4];"
                 : "=r"(r[0]), "=r"(r[1]), "=r"(r[2]), "=r"(r[3]) : "r"(addr));
}
__device__ __forceinline__ void mma_fp16(float* d, const uint32_t* a, uint32_t b0, uint32_t b1) {
    asm volatile(
        "mma.sync.aligned.m16n8k16.row.col.f32.f16.f16.f32 "
        "{%0,%1,%2,%3}, {%4,%5,%6,%7}, {%8,%9}, {%0,%1,%2,%3};"
        : "+f"(d[0]), "+f"(d[1]), "+f"(d[2]), "+f"(d[3])
        : "r"(a[0]), "r"(a[1]), "r"(a[2]), "r"(a[3]), "r"(b0), "r"(b1));
}

// ---------------- helpers ------------------------------------------------------
__device__ __forceinline__ void split1h(float v, __half& h, __half& l) {
    h = __float2half(v);
    l = __float2half(v - __half2float(h));
}

// kernel #2: convert x -> fp16 hi/lo
__global__ void __launch_bounds__(256) conv_x_kernel(const float4* __restrict__ x) {
    size_t i = (size_t)blockIdx.x * 256 + threadIdx.x;
    float4 v = x[i];
    __half h0, h1, h2, h3, l0, l1, l2, l3;
    split1h(v.x, h0, l0); split1h(v.y, h1, l1); split1h(v.z, h2, l2); split1h(v.w, h3, l3);
    __half2* hi = reinterpret_cast<__half2*>(g_xhi);
    __half2* lo = reinterpret_cast<__half2*>(g_xlo);
    hi[2 * i]     = __halves2half2(h0, h1);
    hi[2 * i + 1] = __halves2half2(h2, h3);
    lo[2 * i]     = __halves2half2(l0, l1);
    lo[2 * i + 1] = __halves2half2(l2, l3);
}

// kernel #1: T partials. Block = 64 m-rows, K-slice 1024. Thread: 2 m-rows x 4 r.
#define T_XM_ELEMS (64 * 132)
#define T_SMEM_BYTES (T_XM_ELEMS * 4 + 128 * 8 * 16)   // 50176
__global__ void __launch_bounds__(256) t_partial_kernel(const float* __restrict__ x,
                                                        const float* __restrict__ mask,
                                                        const float* __restrict__ A) {
    extern __shared__ __align__(16) char tsm[];
    float* xm = reinterpret_cast<float*>(tsm);
    float4* a_sm = reinterpret_cast<float4*>(tsm + T_XM_ELEMS * 4);
    const int tid = threadIdx.x;
    const int m0 = blockIdx.x * 64;
    const int slice = blockIdx.y;
    const int kbase = slice * (K_ALL / TSLICES);
    const int mq = tid >> 3;
    const int rg = tid & 7;
    float acc[2][4];
#pragma unroll
    for (int u = 0; u < 2; ++u)
#pragma unroll
        for (int j = 0; j < 4; ++j) acc[u][j] = 0.f;

    const float4* x4 = reinterpret_cast<const float4*>(x);
    const float4* m4 = reinterpret_cast<const float4*>(mask);

    for (int kc = 0; kc < K_ALL / TSLICES; kc += 128) {
        __syncthreads();
#pragma unroll
        for (int i = 0; i < 8; ++i) {
            int idx = tid + i * 256;
            int row = idx >> 5, c4 = idx & 31;
            size_t g = ((size_t)(m0 + row) * K_ALL + kbase + kc) / 4 + c4;
            float4 xv = x4[g];
            float4 mv = m4[g];
            float* dst = &xm[row * 132 + c4 * 4];
            dst[0] = xv.x * mv.x; dst[1] = xv.y * mv.y;
            dst[2] = xv.z * mv.z; dst[3] = xv.w * mv.w;
        }
        const float4* a4 = reinterpret_cast<const float4*>(A) + (size_t)(kbase + kc) * 8;
#pragma unroll
        for (int i = 0; i < 4; ++i) a_sm[tid + i * 256] = a4[tid + i * 256];
        __syncthreads();
#pragma unroll 4
        for (int k = 0; k < 128; ++k) {
            float4 av = a_sm[k * 8 + rg];
            float x0 = xm[(mq * 2) * 132 + k];
            float x1 = xm[(mq * 2 + 1) * 132 + k];
            acc[0][0] += x0 * av.x; acc[0][1] += x0 * av.y;
            acc[0][2] += x0 * av.z; acc[0][3] += x0 * av.w;
            acc[1][0] += x1 * av.x; acc[1][1] += x1 * av.y;
            acc[1][2] += x1 * av.z; acc[1][3] += x1 * av.w;
        }
    }
#pragma unroll
    for (int u = 0; u < 2; ++u) {
        float* dst = &g_tpart[slice][m0 + mq * 2 + u][rg * 4];
        dst[0] = acc[u][0]; dst[1] = acc[u][1]; dst[2] = acc[u][2]; dst[3] = acc[u][3];
    }
}

// kernel #3 (fused): conv W->fp16 (16384 blocks) + B pack (16) + t_pack (256)
__global__ void __launch_bounds__(256) fused_prep_kernel(const float4* __restrict__ W,
                                                         const float* __restrict__ Bm) {
    const int b = blockIdx.x;
    const int tid = threadIdx.x;
    if (b < 16384) {
        size_t i = (size_t)b * 256 + tid;
        float4 v = W[i];
        __half2* hi = reinterpret_cast<__half2*>(g_whi);
        hi[2 * i]     = __halves2half2(__float2half(v.x), __float2half(v.y));
        hi[2 * i + 1] = __halves2half2(__float2half(v.z), __float2half(v.w));
    } else if (b < 16400) {
        int n = (b - 16384) * 256 + tid;
        __half* row = g_btcat + (size_t)n * 64;
#pragma unroll
        for (int r = 0; r < RNK; ++r) {
            __half h = __float2half(Bm[(size_t)r * N_ALL + n]);
            row[r] = h; row[32 + r] = h;
        }
    } else {
        int idx = (b - 16400) * 256 + tid;       // 65536 = 8192 m x 8 rgroups
        int m = idx >> 3, rg = idx & 7, r = rg * 4;
        __half* row = g_tcat + (size_t)m * 64;
#pragma unroll
        for (int j = 0; j < 4; ++j) {
            float s = 0.f;
#pragma unroll
            for (int sl = 0; sl < TSLICES; ++sl) s += g_tpart[sl][m][r + j];
            __half h, l;
            split1h(s, h, l);
            row[r + j] = h; row[32 + r + j] = l;
        }
    }
}

// ---------------- fused GEMM ---------------------------------------------------
// CTA tile 128x128, 256 threads (8 warps = 2M x 4N, warp tile 64x32), 2 CTAs/SM.
// 129 K-chunks of 64:  [0,64): xh@Wh   [64,128): xl@Wh   [128]: [Th|Tl]@[Bh|Bh]
#define NCHUNK 129
#define PITCH_B 144
#define A_BYTES (128 * PITCH_B)
#define B_BYTES (128 * PITCH_B)
#define STAGE_BYTES (A_BYTES + B_BYTES)  // 36864
#define NSTAGE 3
#define GEMM_SMEM (NSTAGE * STAGE_BYTES) // 110592

__device__ __forceinline__ void load_chunk(int c, int stage, int tid, int m0, int n0,
                                           uint32_t smem_base) {
    const __half *pa, *pb;
    int lda, ldb, k0;
    if (c < 64)       { pa = g_xhi;  pb = g_whi;   lda = K_ALL; ldb = K_ALL; k0 = c << 6; }
    else if (c < 128) { pa = g_xlo;  pb = g_whi;   lda = K_ALL; ldb = K_ALL; k0 = (c - 64) << 6; }
    else              { pa = g_tcat; pb = g_btcat; lda = 64;    ldb = 64;    k0 = 0; }
    uint32_t sA = smem_base + stage * STAGE_BYTES;
    uint32_t sB = sA + A_BYTES;
#pragma unroll
    for (int i = 0; i < 4; ++i) {                 // A: 128 rows x 8 x 16B
        int op = tid + i * 256;
        int row = op >> 3, col = op & 7;
        const __half* src = pa + (size_t)(m0 + row) * lda + k0 + col * 8;
        CP_ASYNC16(sA + (uint32_t)(row * PITCH_B + col * 16), src);
    }
#pragma unroll
    for (int i = 0; i < 4; ++i) {                 // B: 128 rows x 8 x 16B
        int op = tid + i * 256;
        int row = op >> 3, col = op & 7;
        const __half* src = pb + (size_t)(n0 + row) * ldb + k0 + col * 8;
        CP_ASYNC16(sB + (uint32_t)(row * PITCH_B + col * 16), src);
    }
}

// kernel #4: the GEMM
__global__ void __launch_bounds__(256, 2)
lora_gemm_kernel(float* __restrict__ out) {
    extern __shared__ __align__(1024) char smem[];
    const uint32_t smem_base = smem_u32(smem);
    const int tid = threadIdx.x;
    const int wid = tid >> 5;
    const int lane = tid & 31;
    // raster: groups of 16 m-tiles x 32 n-tiles
    const int gid = blockIdx.x >> 9;
    const int rr  = blockIdx.x & 511;
    const int m0 = (gid * 16 + (rr & 15)) * 128;
    const int n0 = (rr >> 4) * 128;
    const int m_w = (wid >> 2) * 64;
    const int n_w = (wid & 3) * 32;

    uint32_t aoff[4];
#pragma unroll
    for (int f = 0; f < 4; ++f)
        aoff[f] = (uint32_t)((m_w + f * 16 + (lane & 15)) * PITCH_B + (lane >> 4) * 16);
    uint32_t boff[2];
#pragma unroll
    for (int jj = 0; jj < 2; ++jj)
        boff[jj] = (uint32_t)(A_BYTES +
                              (n_w + jj * 16 + ((lane >> 4) << 3) + (lane & 7)) * PITCH_B +
                              ((lane >> 3) & 1) * 16);

    float acc[4][4][4];
#pragma unroll
    for (int f = 0; f < 4; ++f)
#pragma unroll
        for (int j = 0; j < 4; ++j)
#pragma unroll
            for (int v = 0; v < 4; ++v) acc[f][j][v] = 0.f;

    load_chunk(0, 0, tid, m0, n0, smem_base);
    CP_ASYNC_COMMIT();
    load_chunk(1, 1, tid, m0, n0, smem_base);
    CP_ASYNC_COMMIT();

    int st_c = 0, st_l = 2;
    for (int c = 0; c < NCHUNK; ++c) {
        CP_ASYNC_WAIT(1);
        __syncthreads();
        const int cl = c + 2;
        if (cl < NCHUNK) load_chunk(cl, st_l, tid, m0, n0, smem_base);
        CP_ASYNC_COMMIT();

        const uint32_t sbase = smem_base + st_c * STAGE_BYTES;
#pragma unroll
        for (int ks = 0; ks < 4; ++ks) {
            uint32_t a[4][4], b[2][4];
#pragma unroll
            for (int f = 0; f < 4; ++f) ldmatrix_x4(a[f], sbase + aoff[f] + ks * 32);
#pragma unroll
            for (int jj = 0; jj < 2; ++jj) ldmatrix_x4(b[jj], sbase + boff[jj] + ks * 32);
#pragma unroll
            for (int f = 0; f < 4; ++f)
#pragma unroll
                for (int j = 0; j < 4; ++j)
                    mma_fp16(acc[f][j], a[f], b[j >> 1][(j & 1) * 2], b[j >> 1][(j & 1) * 2 + 1]);
        }
        st_c = (st_c + 1 == NSTAGE) ? 0 : st_c + 1;
        st_l = (st_l + 1 == NSTAGE) ? 0 : st_l + 1;
    }

    // epilogue
    const int g8 = lane >> 2;
    const int t4 = lane & 3;
#pragma unroll
    for (int f = 0; f < 4; ++f) {
        const int mrow = m0 + m_w + f * 16 + g8;
#pragma unroll
        for (int j = 0; j < 4; ++j) {
            const int ncol = n0 + n_w + j * 8 + t4 * 2;
            float2 v0 = make_float2(acc[f][j][0], acc[f][j][1]);
            float2 v1 = make_float2(acc[f][j][2], acc[f][j][3]);
            *reinterpret_cast<float2*>(out + (size_t)mrow * N_ALL + ncol) = v0;
            *reinterpret_cast<float2*>(out + (size_t)(mrow + 8) * N_ALL + ncol) = v1;
        }
    }
}

// ---------------- launch ---------------------------------------------------------
extern "C" void kernel_launch(void* const* d_in, const int* in_sizes, int n_in,
                              void* d_out, int out_size) {
    const float* x    = (const float*)d_in[0];   // [8192, 4096]
    const float* W    = (const float*)d_in[1];   // [4096, 4096]
    const float* A    = (const float*)d_in[2];   // [4096, 32]
    const float* Bm   = (const float*)d_in[3];   // [32, 4096]
    const float* mask = (const float*)d_in[4];   // [8192, 4096]
    float* out = (float*)d_out;

    static bool attr_set = false;
    if (!attr_set) {
        cudaFuncSetAttribute(lora_gemm_kernel,
                             cudaFuncAttributeMaxDynamicSharedMemorySize, GEMM_SMEM);
        cudaFuncSetAttribute(t_partial_kernel,
                             cudaFuncAttributeMaxDynamicSharedMemorySize, T_SMEM_BYTES);
        attr_set = true;
    }

    // GEMM is the 4th launch (profiler capture slot)
    t_partial_kernel<<<dim3(128, TSLICES), 256, T_SMEM_BYTES>>>(x, mask, A);
    conv_x_kernel<<<32768, 256>>>((const float4*)x);
    fused_prep_kernel<<<16656, 256>>>((const float4*)W, Bm);
    lora_gemm_kernel<<<2048, 256, GEMM_SMEM>>>(out);
}

// round 8
// speedup vs baseline: 3.0013x; 1.7771x over previous
#include <cuda_runtime.h>
#include <cuda_fp16.h>
#include <cstdint>

// out[8192,4096] = x@W^T + ((x*mask)@A)@B   (fp32, SCALE=1)
// Single-pass fp16: xh=fp16(x), Wh=fp16(W). Error = x-quant + W-quant (~3e-4 rel).
// LoRA band exact-T: [Th|Tl] @ [Bh|Bh].
#define M_ALL 8192
#define N_ALL 4096
#define K_ALL 4096
#define RNK   32
#define TSLICES 4

// ---------------- scratch (__device__ globals; no allocs allowed) ------------
__device__ __align__(256) __half g_xhi[(size_t)M_ALL * K_ALL];
__device__ __align__(256) __half g_whi[(size_t)N_ALL * K_ALL];
__device__ __align__(256) __half g_tcat[(size_t)M_ALL * 64];    // [Th|Tl]
__device__ __align__(256) __half g_btcat[(size_t)N_ALL * 64];   // [Bh|Bh]
__device__ __align__(256) float g_tpart[TSLICES][M_ALL][RNK];

// ---------------- PTX helpers -------------------------------------------------
__device__ __forceinline__ uint32_t smem_u32(const void* p) {
    uint32_t a;
    asm("{ .reg .u64 t; cvta.to.shared.u64 t, %1; cvt.u32.u64 %0, t; }" : "=r"(a) : "l"(p));
    return a;
}
#define CP_ASYNC16(dst, src) \
    asm volatile("cp.async.cg.shared.global [%0], [%1], 16;" :: "r"((uint32_t)(dst)), "l"(src))
#define CP_ASYNC_COMMIT() asm volatile("cp.async.commit_group;" ::: "memory")
#define CP_ASYNC_WAIT(n)  asm volatile("cp.async.wait_group %0;" :: "n"(n) : "memory")

__device__ __forceinline__ void ldmatrix_x4(uint32_t* r, uint32_t addr) {
    asm volatile("ldmatrix.sync.aligned.m8n8.x4.shared.b16 {%0,%1,%2,%3}, [%4];"
                 : "=r"(r[0]), "=r"(r[1]), "=r"(r[2]), "=r"(r[3]) : "r"(addr));
}
__device__ __forceinline__ void mma_fp16(float* d, const uint32_t* a, uint32_t b0, uint32_t b1) {
    asm volatile(
        "mma.sync.aligned.m16n8k16.row.col.f32.f16.f16.f32 "
        "{%0,%1,%2,%3}, {%4,%5,%6,%7}, {%8,%9}, {%0,%1,%2,%3};"
        : "+f"(d[0]), "+f"(d[1]), "+f"(d[2]), "+f"(d[3])
        : "r"(a[0]), "r"(a[1]), "r"(a[2]), "r"(a[3]), "r"(b0), "r"(b1));
}

// ---------------- helpers ------------------------------------------------------
__device__ __forceinline__ void split1h(float v, __half& h, __half& l) {
    h = __float2half(v);
    l = __float2half(v - __half2float(h));
}

// kernel #2: convert x -> fp16 (single plane)
__global__ void __launch_bounds__(256) conv_x_kernel(const float4* __restrict__ x) {
    size_t i = (size_t)blockIdx.x * 256 + threadIdx.x;
    float4 v = x[i];
    __half2* hi = reinterpret_cast<__half2*>(g_xhi);
    hi[2 * i]     = __halves2half2(__float2half(v.x), __float2half(v.y));
    hi[2 * i + 1] = __halves2half2(__float2half(v.z), __float2half(v.w));
}

// kernel #1: T partials. Block = 128 m-rows, K-slice 1024. Thread: 4 m-rows x 4 r.
#define T_XM_ELEMS (128 * 132)
#define T_SMEM_BYTES (T_XM_ELEMS * 4 + 128 * 8 * 16)   // 67584 + 16384 = 83968
__global__ void __launch_bounds__(256) t_partial_kernel(const float* __restrict__ x,
                                                        const float* __restrict__ mask,
                                                        const float* __restrict__ A) {
    extern __shared__ __align__(16) char tsm[];
    float* xm = reinterpret_cast<float*>(tsm);
    float4* a_sm = reinterpret_cast<float4*>(tsm + T_XM_ELEMS * 4);
    const int tid = threadIdx.x;
    const int m0 = blockIdx.x * 128;
    const int slice = blockIdx.y;
    const int kbase = slice * (K_ALL / TSLICES);
    const int mq = tid >> 3;          // 0..31 -> rows 4*mq..4*mq+3
    const int rg = tid & 7;           // 0..7  -> r = rg*4
    float acc[4][4];
#pragma unroll
    for (int u = 0; u < 4; ++u)
#pragma unroll
        for (int j = 0; j < 4; ++j) acc[u][j] = 0.f;

    const float4* x4 = reinterpret_cast<const float4*>(x);
    const float4* m4 = reinterpret_cast<const float4*>(mask);

    for (int kc = 0; kc < K_ALL / TSLICES; kc += 128) {
        __syncthreads();
#pragma unroll
        for (int i = 0; i < 16; ++i) {            // 4096 float4: 128 rows x 32 f4
            int idx = tid + i * 256;
            int row = idx >> 5, c4 = idx & 31;
            size_t g = ((size_t)(m0 + row) * K_ALL + kbase + kc) / 4 + c4;
            float4 xv = x4[g];
            float4 mv = m4[g];
            float* dst = &xm[row * 132 + c4 * 4];
            dst[0] = xv.x * mv.x; dst[1] = xv.y * mv.y;
            dst[2] = xv.z * mv.z; dst[3] = xv.w * mv.w;
        }
        const float4* a4 = reinterpret_cast<const float4*>(A) + (size_t)(kbase + kc) * 8;
#pragma unroll
        for (int i = 0; i < 4; ++i) a_sm[tid + i * 256] = a4[tid + i * 256];
        __syncthreads();
#pragma unroll 2
        for (int k = 0; k < 128; ++k) {
            float4 av = a_sm[k * 8 + rg];
#pragma unroll
            for (int u = 0; u < 4; ++u) {
                float xv = xm[(mq * 4 + u) * 132 + k];
                acc[u][0] += xv * av.x; acc[u][1] += xv * av.y;
                acc[u][2] += xv * av.z; acc[u][3] += xv * av.w;
            }
        }
    }
#pragma unroll
    for (int u = 0; u < 4; ++u) {
        float* dst = &g_tpart[slice][m0 + mq * 4 + u][rg * 4];
        dst[0] = acc[u][0]; dst[1] = acc[u][1]; dst[2] = acc[u][2]; dst[3] = acc[u][3];
    }
}

// kernel #3 (fused): conv W->fp16 (16384 blocks) + B pack (16) + t_pack (256)
__global__ void __launch_bounds__(256) fused_prep_kernel(const float4* __restrict__ W,
                                                         const float* __restrict__ Bm) {
    const int b = blockIdx.x;
    const int tid = threadIdx.x;
    if (b < 16384) {
        size_t i = (size_t)b * 256 + tid;
        float4 v = W[i];
        __half2* hi = reinterpret_cast<__half2*>(g_whi);
        hi[2 * i]     = __halves2half2(__float2half(v.x), __float2half(v.y));
        hi[2 * i + 1] = __halves2half2(__float2half(v.z), __float2half(v.w));
    } else if (b < 16400) {
        int n = (b - 16384) * 256 + tid;
        __half* row = g_btcat + (size_t)n * 64;
#pragma unroll
        for (int r = 0; r < RNK; ++r) {
            __half h = __float2half(Bm[(size_t)r * N_ALL + n]);
            row[r] = h; row[32 + r] = h;
        }
    } else {
        int idx = (b - 16400) * 256 + tid;       // 65536 = 8192 m x 8 rgroups
        int m = idx >> 3, rg = idx & 7, r = rg * 4;
        __half* row = g_tcat + (size_t)m * 64;
#pragma unroll
        for (int j = 0; j < 4; ++j) {
            float s = 0.f;
#pragma unroll
            for (int sl = 0; sl < TSLICES; ++sl) s += g_tpart[sl][m][r + j];
            __half h, l;
            split1h(s, h, l);
            row[r + j] = h; row[32 + r + j] = l;
        }
    }
}

// ---------------- fused GEMM ---------------------------------------------------
// CTA tile 128x128, 256 threads (8 warps = 2M x 4N, warp tile 64x32), 2 CTAs/SM.
// 65 K-chunks of 64:  [0,64): xh@Wh   [64]: [Th|Tl]@[Bh|Bh]
#define NCHUNK 65
#define PITCH_B 144
#define A_BYTES (128 * PITCH_B)
#define B_BYTES (128 * PITCH_B)
#define STAGE_BYTES (A_BYTES + B_BYTES)  // 36864
#define NSTAGE 3
#define GEMM_SMEM (NSTAGE * STAGE_BYTES) // 110592

__device__ __forceinline__ void load_chunk(int c, int stage, int tid, int m0, int n0,
                                           uint32_t smem_base) {
    const __half *pa, *pb;
    int lda, ldb, k0;
    if (c < 64) { pa = g_xhi;  pb = g_whi;   lda = K_ALL; ldb = K_ALL; k0 = c << 6; }
    else        { pa = g_tcat; pb = g_btcat; lda = 64;    ldb = 64;    k0 = 0; }
    uint32_t sA = smem_base + stage * STAGE_BYTES;
    uint32_t sB = sA + A_BYTES;
#pragma unroll
    for (int i = 0; i < 4; ++i) {                 // A: 128 rows x 8 x 16B
        int op = tid + i * 256;
        int row = op >> 3, col = op & 7;
        const __half* src = pa + (size_t)(m0 + row) * lda + k0 + col * 8;
        CP_ASYNC16(sA + (uint32_t)(row * PITCH_B + col * 16), src);
    }
#pragma unroll
    for (int i = 0; i < 4; ++i) {                 // B: 128 rows x 8 x 16B
        int op = tid + i * 256;
        int row = op >> 3, col = op & 7;
        const __half* src = pb + (size_t)(n0 + row) * ldb + k0 + col * 8;
        CP_ASYNC16(sB + (uint32_t)(row * PITCH_B + col * 16), src);
    }
}

// kernel #4: the GEMM
__global__ void __launch_bounds__(256, 2)
lora_gemm_kernel(float* __restrict__ out) {
    extern __shared__ __align__(1024) char smem[];
    const uint32_t smem_base = smem_u32(smem);
    const int tid = threadIdx.x;
    const int wid = tid >> 5;
    const int lane = tid & 31;
    // raster: groups of 16 m-tiles x 32 n-tiles
    const int gid = blockIdx.x >> 9;
    const int rr  = blockIdx.x & 511;
    const int m0 = (gid * 16 + (rr & 15)) * 128;
    const int n0 = (rr >> 4) * 128;
    const int m_w = (wid >> 2) * 64;
    const int n_w = (wid & 3) * 32;

    uint32_t aoff[4];
#pragma unroll
    for (int f = 0; f < 4; ++f)
        aoff[f] = (uint32_t)((m_w + f * 16 + (lane & 15)) * PITCH_B + (lane >> 4) * 16);
    uint32_t boff[2];
#pragma unroll
    for (int jj = 0; jj < 2; ++jj)
        boff[jj] = (uint32_t)(A_BYTES +
                              (n_w + jj * 16 + ((lane >> 4) << 3) + (lane & 7)) * PITCH_B +
                              ((lane >> 3) & 1) * 16);

    float acc[4][4][4];
#pragma unroll
    for (int f = 0; f < 4; ++f)
#pragma unroll
        for (int j = 0; j < 4; ++j)
#pragma unroll
            for (int v = 0; v < 4; ++v) acc[f][j][v] = 0.f;

    load_chunk(0, 0, tid, m0, n0, smem_base);
    CP_ASYNC_COMMIT();
    load_chunk(1, 1, tid, m0, n0, smem_base);
    CP_ASYNC_COMMIT();

    int st_c = 0, st_l = 2;
    for (int c = 0; c < NCHUNK; ++c) {
        CP_ASYNC_WAIT(1);
        __syncthreads();
        const int cl = c + 2;
        if (cl < NCHUNK) load_chunk(cl, st_l, tid, m0, n0, smem_base);
        CP_ASYNC_COMMIT();

        const uint32_t sbase = smem_base + st_c * STAGE_BYTES;
#pragma unroll
        for (int ks = 0; ks < 4; ++ks) {
            uint32_t a[4][4], b[2][4];
#pragma unroll
            for (int f = 0; f < 4; ++f) ldmatrix_x4(a[f], sbase + aoff[f] + ks * 32);
#pragma unroll
            for (int jj = 0; jj < 2; ++jj) ldmatrix_x4(b[jj], sbase + boff[jj] + ks * 32);
#pragma unroll
            for (int f = 0; f < 4; ++f)
#pragma unroll
                for (int j = 0; j < 4; ++j)
                    mma_fp16(acc[f][j], a[f], b[j >> 1][(j & 1) * 2], b[j >> 1][(j & 1) * 2 + 1]);
        }
        st_c = (st_c + 1 == NSTAGE) ? 0 : st_c + 1;
        st_l = (st_l + 1 == NSTAGE) ? 0 : st_l + 1;
    }

    // epilogue
    const int g8 = lane >> 2;
    const int t4 = lane & 3;
#pragma unroll
    for (int f = 0; f < 4; ++f) {
        const int mrow = m0 + m_w + f * 16 + g8;
#pragma unroll
        for (int j = 0; j < 4; ++j) {
            const int ncol = n0 + n_w + j * 8 + t4 * 2;
            float2 v0 = make_float2(acc[f][j][0], acc[f][j][1]);
            float2 v1 = make_float2(acc[f][j][2], acc[f][j][3]);
            *reinterpret_cast<float2*>(out + (size_t)mrow * N_ALL + ncol) = v0;
            *reinterpret_cast<float2*>(out + (size_t)(mrow + 8) * N_ALL + ncol) = v1;
        }
    }
}

// ---------------- launch ---------------------------------------------------------
extern "C" void kernel_launch(void* const* d_in, const int* in_sizes, int n_in,
                              void* d_out, int out_size) {
    const float* x    = (const float*)d_in[0];   // [8192, 4096]
    const float* W    = (const float*)d_in[1];   // [4096, 4096]
    const float* A    = (const float*)d_in[2];   // [4096, 32]
    const float* Bm   = (const float*)d_in[3];   // [32, 4096]
    const float* mask = (const float*)d_in[4];   // [8192, 4096]
    float* out = (float*)d_out;

    static bool attr_set = false;
    if (!attr_set) {
        cudaFuncSetAttribute(lora_gemm_kernel,
                             cudaFuncAttributeMaxDynamicSharedMemorySize, GEMM_SMEM);
        cudaFuncSetAttribute(t_partial_kernel,
                             cudaFuncAttributeMaxDynamicSharedMemorySize, T_SMEM_BYTES);
        attr_set = true;
    }

    // GEMM is the 4th launch (profiler capture slot)
    t_partial_kernel<<<dim3(64, TSLICES), 256, T_SMEM_BYTES>>>(x, mask, A);
    conv_x_kernel<<<32768, 256>>>((const float4*)x);
    fused_prep_kernel<<<16656, 256>>>((const float4*)W, Bm);
    lora_gemm_kernel<<<2048, 256, GEMM_SMEM>>>(out);
}

// round 9
// speedup vs baseline: 3.2832x; 1.0939x over previous
#include <cuda_runtime.h>
#include <cuda_fp16.h>
#include <cstdint>

// out[8192,4096] = x@W^T + ((x*mask)@A)@B   (fp32, SCALE=1)
// Single-pass fp16: xh=fp16(x), Wh=fp16(W). LoRA band exact-T: [Th|Tl]@[Bh|Bh].
#define M_ALL 8192
#define N_ALL 4096
#define K_ALL 4096
#define RNK   32
#define TSLICES 4

// ---------------- scratch (__device__ globals; no allocs allowed) ------------
__device__ __align__(256) __half g_xhi[(size_t)M_ALL * K_ALL];
__device__ __align__(256) __half g_whi[(size_t)N_ALL * K_ALL];
__device__ __align__(256) __half g_tcat[(size_t)M_ALL * 64];    // [Th|Tl]
__device__ __align__(256) __half g_btcat[(size_t)N_ALL * 64];   // [Bh|Bh]
__device__ __align__(256) float g_tpart[TSLICES][M_ALL][RNK];

// ---------------- PTX helpers -------------------------------------------------
__device__ __forceinline__ uint32_t smem_u32(const void* p) {
    uint32_t a;
    asm("{ .reg .u64 t; cvta.to.shared.u64 t, %1; cvt.u32.u64 %0, t; }" : "=r"(a) : "l"(p));
    return a;
}
#define CP_ASYNC16(dst, src) \
    asm volatile("cp.async.cg.shared.global [%0], [%1], 16;" :: "r"((uint32_t)(dst)), "l"(src))
#define CP_ASYNC_COMMIT() asm volatile("cp.async.commit_group;" ::: "memory")
#define CP_ASYNC_WAIT(n)  asm volatile("cp.async.wait_group %0;" :: "n"(n) : "memory")

__device__ __forceinline__ void ldmatrix_x4(uint32_t* r, uint32_t addr) {
    asm volatile("ldmatrix.sync.aligned.m8n8.x4.shared.b16 {%0,%1,%2,%3}, [%4];"
                 : "=r"(r[0]), "=r"(r[1]), "=r"(r[2]), "=r"(r[3]) : "r"(addr));
}
__device__ __forceinline__ void mma_fp16(float* d, const uint32_t* a, uint32_t b0, uint32_t b1) {
    asm volatile(
        "mma.sync.aligned.m16n8k16.row.col.f32.f16.f16.f32 "
        "{%0,%1,%2,%3}, {%4,%5,%6,%7}, {%8,%9}, {%0,%1,%2,%3};"
        : "+f"(d[0]), "+f"(d[1]), "+f"(d[2]), "+f"(d[3])
        : "r"(a[0]), "r"(a[1]), "r"(a[2]), "r"(a[3]), "r"(b0), "r"(b1));
}

// ---------------- helpers ------------------------------------------------------
__device__ __forceinline__ void split1h(float v, __half& h, __half& l) {
    h = __float2half(v);
    l = __float2half(v - __half2float(h));
}

// kernel #1: T partials + x->fp16 conversion fused.
// Block = 128 m-rows, K-slice 1024. Thread: 4 m-rows x 4 r. Covers each (m,k) once.
#define T_XM_ELEMS (128 * 132)
#define T_SMEM_BYTES (T_XM_ELEMS * 4 + 128 * 8 * 16)   // 83968
__global__ void __launch_bounds__(256) t_partial_kernel(const float* __restrict__ x,
                                                        const float* __restrict__ mask,
                                                        const float* __restrict__ A) {
    extern __shared__ __align__(16) char tsm[];
    float* xm = reinterpret_cast<float*>(tsm);
    float4* a_sm = reinterpret_cast<float4*>(tsm + T_XM_ELEMS * 4);
    const int tid = threadIdx.x;
    const int m0 = blockIdx.x * 128;
    const int slice = blockIdx.y;
    const int kbase = slice * (K_ALL / TSLICES);
    const int mq = tid >> 3;
    const int rg = tid & 7;
    float acc[4][4];
#pragma unroll
    for (int u = 0; u < 4; ++u)
#pragma unroll
        for (int j = 0; j < 4; ++j) acc[u][j] = 0.f;

    const float4* x4 = reinterpret_cast<const float4*>(x);
    const float4* m4 = reinterpret_cast<const float4*>(mask);
    __half2* xh2 = reinterpret_cast<__half2*>(g_xhi);

    for (int kc = 0; kc < K_ALL / TSLICES; kc += 128) {
        __syncthreads();
#pragma unroll
        for (int i = 0; i < 16; ++i) {            // 4096 float4: 128 rows x 32 f4
            int idx = tid + i * 256;
            int row = idx >> 5, c4 = idx & 31;
            size_t g = ((size_t)(m0 + row) * K_ALL + kbase + kc) / 4 + c4;
            float4 xv = x4[g];
            float4 mv = m4[g];
            // fused x -> fp16 conversion (each (m,k) visited exactly once globally)
            xh2[2 * g]     = __halves2half2(__float2half(xv.x), __float2half(xv.y));
            xh2[2 * g + 1] = __halves2half2(__float2half(xv.z), __float2half(xv.w));
            float* dst = &xm[row * 132 + c4 * 4];
            dst[0] = xv.x * mv.x; dst[1] = xv.y * mv.y;
            dst[2] = xv.z * mv.z; dst[3] = xv.w * mv.w;
        }
        const float4* a4 = reinterpret_cast<const float4*>(A) + (size_t)(kbase + kc) * 8;
#pragma unroll
        for (int i = 0; i < 4; ++i) a_sm[tid + i * 256] = a4[tid + i * 256];
        __syncthreads();
#pragma unroll 2
        for (int k = 0; k < 128; ++k) {
            float4 av = a_sm[k * 8 + rg];
#pragma unroll
            for (int u = 0; u < 4; ++u) {
                float xv = xm[(mq * 4 + u) * 132 + k];
                acc[u][0] += xv * av.x; acc[u][1] += xv * av.y;
                acc[u][2] += xv * av.z; acc[u][3] += xv * av.w;
            }
        }
    }
#pragma unroll
    for (int u = 0; u < 4; ++u) {
        float* dst = &g_tpart[slice][m0 + mq * 4 + u][rg * 4];
        dst[0] = acc[u][0]; dst[1] = acc[u][1]; dst[2] = acc[u][2]; dst[3] = acc[u][3];
    }
}

// kernel #2 (fused): conv W->fp16 (16384 blocks) + B pack (16) + t_pack (256)
__global__ void __launch_bounds__(256) fused_prep_kernel(const float4* __restrict__ W,
                                                         const float* __restrict__ Bm) {
    const int b = blockIdx.x;
    const int tid = threadIdx.x;
    if (b < 16384) {
        size_t i = (size_t)b * 256 + tid;
        float4 v = W[i];
        __half2* hi = reinterpret_cast<__half2*>(g_whi);
        hi[2 * i]     = __halves2half2(__float2half(v.x), __float2half(v.y));
        hi[2 * i + 1] = __halves2half2(__float2half(v.z), __float2half(v.w));
    } else if (b < 16400) {
        int n = (b - 16384) * 256 + tid;
        __half* row = g_btcat + (size_t)n * 64;
#pragma unroll
        for (int r = 0; r < RNK; ++r) {
            __half h = __float2half(Bm[(size_t)r * N_ALL + n]);
            row[r] = h; row[32 + r] = h;
        }
    } else {
        int idx = (b - 16400) * 256 + tid;       // 65536 = 8192 m x 8 rgroups
        int m = idx >> 3, rg = idx & 7, r = rg * 4;
        __half* row = g_tcat + (size_t)m * 64;
#pragma unroll
        for (int j = 0; j < 4; ++j) {
            float s = 0.f;
#pragma unroll
            for (int sl = 0; sl < TSLICES; ++sl) s += g_tpart[sl][m][r + j];
            __half h, l;
            split1h(s, h, l);
            row[r + j] = h; row[32 + r + j] = l;
        }
    }
}

// ---------------- fused GEMM ---------------------------------------------------
// CTA tile 128x128, 256 threads (8 warps = 2M x 4N, warp tile 64x32), 2 CTAs/SM.
// 65 K-chunks of 64:  [0,64): xh@Wh   [64]: [Th|Tl]@[Bh|Bh]
#define NCHUNK 65
#define PITCH_B 144
#define A_BYTES (128 * PITCH_B)
#define B_BYTES (128 * PITCH_B)
#define STAGE_BYTES (A_BYTES + B_BYTES)  // 36864
#define NSTAGE 3
#define GEMM_SMEM (NSTAGE * STAGE_BYTES) // 110592

__device__ __forceinline__ void load_chunk(int c, int stage, int tid, int m0, int n0,
                                           uint32_t smem_base) {
    const __half *pa, *pb;
    int lda, ldb, k0;
    if (c < 64) { pa = g_xhi;  pb = g_whi;   lda = K_ALL; ldb = K_ALL; k0 = c << 6; }
    else        { pa = g_tcat; pb = g_btcat; lda = 64;    ldb = 64;    k0 = 0; }
    uint32_t sA = smem_base + stage * STAGE_BYTES;
    uint32_t sB = sA + A_BYTES;
#pragma unroll
    for (int i = 0; i < 4; ++i) {                 // A: 128 rows x 8 x 16B
        int op = tid + i * 256;
        int row = op >> 3, col = op & 7;
        const __half* src = pa + (size_t)(m0 + row) * lda + k0 + col * 8;
        CP_ASYNC16(sA + (uint32_t)(row * PITCH_B + col * 16), src);
    }
#pragma unroll
    for (int i = 0; i < 4; ++i) {                 // B: 128 rows x 8 x 16B
        int op = tid + i * 256;
        int row = op >> 3, col = op & 7;
        const __half* src = pb + (size_t)(n0 + row) * ldb + k0 + col * 8;
        CP_ASYNC16(sB + (uint32_t)(row * PITCH_B + col * 16), src);
    }
}

// kernel #3: the GEMM
__global__ void __launch_bounds__(256, 2)
lora_gemm_kernel(float* __restrict__ out) {
    extern __shared__ __align__(1024) char smem[];
    const uint32_t smem_base = smem_u32(smem);
    const int tid = threadIdx.x;
    const int wid = tid >> 5;
    const int lane = tid & 31;
    // raster: groups of 16 m-tiles x 32 n-tiles
    const int gid = blockIdx.x >> 9;
    const int rr  = blockIdx.x & 511;
    const int m0 = (gid * 16 + (rr & 15)) * 128;
    const int n0 = (rr >> 4) * 128;
    const int m_w = (wid >> 2) * 64;
    const int n_w = (wid & 3) * 32;

    uint32_t aoff[4];
#pragma unroll
    for (int f = 0; f < 4; ++f)
        aoff[f] = (uint32_t)((m_w + f * 16 + (lane & 15)) * PITCH_B + (lane >> 4) * 16);
    uint32_t boff[2];
#pragma unroll
    for (int jj = 0; jj < 2; ++jj)
        boff[jj] = (uint32_t)(A_BYTES +
                              (n_w + jj * 16 + ((lane >> 4) << 3) + (lane & 7)) * PITCH_B +
                              ((lane >> 3) & 1) * 16);

    float acc[4][4][4];
#pragma unroll
    for (int f = 0; f < 4; ++f)
#pragma unroll
        for (int j = 0; j < 4; ++j)
#pragma unroll
            for (int v = 0; v < 4; ++v) acc[f][j][v] = 0.f;

    load_chunk(0, 0, tid, m0, n0, smem_base);
    CP_ASYNC_COMMIT();
    load_chunk(1, 1, tid, m0, n0, smem_base);
    CP_ASYNC_COMMIT();

    int st_c = 0, st_l = 2;
    for (int c = 0; c < NCHUNK; ++c) {
        CP_ASYNC_WAIT(1);
        __syncthreads();
        const int cl = c + 2;
        const uint32_t sbase = smem_base + st_c * STAGE_BYTES;

        // per-ks interleave: ld frags(ks) -> mma(ks); next-chunk cp.async issued
        // in the ks==1 slot (inside the mma shadow, not at the barrier).
#pragma unroll
        for (int ks = 0; ks < 4; ++ks) {
            uint32_t a[4][4], b[2][4];
#pragma unroll
            for (int jj = 0; jj < 2; ++jj) ldmatrix_x4(b[jj], sbase + boff[jj] + ks * 32);
#pragma unroll
            for (int f = 0; f < 4; ++f) ldmatrix_x4(a[f], sbase + aoff[f] + ks * 32);
            if (ks == 1 && cl < NCHUNK) load_chunk(cl, st_l, tid, m0, n0, smem_base);
#pragma unroll
            for (int f = 0; f < 4; ++f)
#pragma unroll
                for (int j = 0; j < 4; ++j)
                    mma_fp16(acc[f][j], a[f], b[j >> 1][(j & 1) * 2], b[j >> 1][(j & 1) * 2 + 1]);
        }
        CP_ASYNC_COMMIT();
        st_c = (st_c + 1 == NSTAGE) ? 0 : st_c + 1;
        st_l = (st_l + 1 == NSTAGE) ? 0 : st_l + 1;
    }

    // epilogue
    const int g8 = lane >> 2;
    const int t4 = lane & 3;
#pragma unroll
    for (int f = 0; f < 4; ++f) {
        const int mrow = m0 + m_w + f * 16 + g8;
#pragma unroll
        for (int j = 0; j < 4; ++j) {
            const int ncol = n0 + n_w + j * 8 + t4 * 2;
            float2 v0 = make_float2(acc[f][j][0], acc[f][j][1]);
            float2 v1 = make_float2(acc[f][j][2], acc[f][j][3]);
            *reinterpret_cast<float2*>(out + (size_t)mrow * N_ALL + ncol) = v0;
            *reinterpret_cast<float2*>(out + (size_t)(mrow + 8) * N_ALL + ncol) = v1;
        }
    }
}

// ---------------- launch ---------------------------------------------------------
extern "C" void kernel_launch(void* const* d_in, const int* in_sizes, int n_in,
                              void* d_out, int out_size) {
    const float* x    = (const float*)d_in[0];   // [8192, 4096]
    const float* W    = (const float*)d_in[1];   // [4096, 4096]
    const float* A    = (const float*)d_in[2];   // [4096, 32]
    const float* Bm   = (const float*)d_in[3];   // [32, 4096]
    const float* mask = (const float*)d_in[4];   // [8192, 4096]
    float* out = (float*)d_out;

    static bool attr_set = false;
    if (!attr_set) {
        cudaFuncSetAttribute(lora_gemm_kernel,
                             cudaFuncAttributeMaxDynamicSharedMemorySize, GEMM_SMEM);
        cudaFuncSetAttribute(t_partial_kernel,
                             cudaFuncAttributeMaxDynamicSharedMemorySize, T_SMEM_BYTES);
        attr_set = true;
    }

    t_partial_kernel<<<dim3(64, TSLICES), 256, T_SMEM_BYTES>>>(x, mask, A);
    fused_prep_kernel<<<16656, 256>>>((const float4*)W, Bm);
    lora_gemm_kernel<<<2048, 256, GEMM_SMEM>>>(out);
}

// round 10
// speedup vs baseline: 3.2834x; 1.0001x over previous
#include <cuda_runtime.h>
#include <cuda_fp16.h>
#include <cstdint>

// out[8192,4096] = x@W^T + ((x*mask)@A)@B   (fp32, SCALE=1)
// Single-pass fp16: xh=fp16(x), Wh=fp16(W). LoRA band exact-T: [Th|Tl]@[Bh|Bh].
#define M_ALL 8192
#define N_ALL 4096
#define K_ALL 4096
#define RNK   32
#define TSLICES 4

// ---------------- scratch (__device__ globals; no allocs allowed) ------------
__device__ __align__(256) __half g_xhi[(size_t)M_ALL * K_ALL];
__device__ __align__(256) __half g_whi[(size_t)N_ALL * K_ALL];
__device__ __align__(256) __half g_tcat[(size_t)M_ALL * 64];    // [Th|Tl]
__device__ __align__(256) __half g_btcat[(size_t)N_ALL * 64];   // [Bh|Bh]
__device__ __align__(256) float g_tpart[TSLICES][M_ALL][RNK];

// ---------------- PTX helpers -------------------------------------------------
__device__ __forceinline__ uint32_t smem_u32(const void* p) {
    uint32_t a;
    asm("{ .reg .u64 t; cvta.to.shared.u64 t, %1; cvt.u32.u64 %0, t; }" : "=r"(a) : "l"(p));
    return a;
}
#define CP_ASYNC16(dst, src) \
    asm volatile("cp.async.cg.shared.global [%0], [%1], 16;" :: "r"((uint32_t)(dst)), "l"(src))
#define CP_ASYNC_COMMIT() asm volatile("cp.async.commit_group;" ::: "memory")
#define CP_ASYNC_WAIT(n)  asm volatile("cp.async.wait_group %0;" :: "n"(n) : "memory")

__device__ __forceinline__ void ldmatrix_x4(uint32_t* r, uint32_t addr) {
    asm volatile("ldmatrix.sync.aligned.m8n8.x4.shared.b16 {%0,%1,%2,%3}, [%4];"
                 : "=r"(r[0]), "=r"(r[1]), "=r"(r[2]), "=r"(r[3]) : "r"(addr));
}
__device__ __forceinline__ void mma_fp16(float* d, const uint32_t* a, uint32_t b0, uint32_t b1) {
    asm volatile(
        "mma.sync.aligned.m16n8k16.row.col.f32.f16.f16.f32 "
        "{%0,%1,%2,%3}, {%4,%5,%6,%7}, {%8,%9}, {%0,%1,%2,%3};"
        : "+f"(d[0]), "+f"(d[1]), "+f"(d[2]), "+f"(d[3])
        : "r"(a[0]), "r"(a[1]), "r"(a[2]), "r"(a[3]), "r"(b0), "r"(b1));
}
__device__ __forceinline__ void split1h(float v, __half& h, __half& l) {
    h = __float2half(v);
    l = __float2half(v - __half2float(h));
}

// ---------------- kernel #1: T partials + x->fp16 + W->fp16 (merged grid) ------
// bid < 512: t-block (64 m-rows, K-slice 1024, fused x conversion)
// bid >= 512: W conversion block (DRAM-bound filler work)
#define T_BLOCKS 512
#define W_BLOCKS 16384
#define T_XM_ELEMS (64 * 132)
#define T_SMEM_BYTES (T_XM_ELEMS * 4 + 128 * 8 * 16)   // 33792 + 16384 = 50176
__global__ void __launch_bounds__(256) prep1_kernel(const float* __restrict__ x,
                                                    const float* __restrict__ mask,
                                                    const float* __restrict__ A,
                                                    const float4* __restrict__ W) {
    extern __shared__ __align__(16) char tsm[];
    const int tid = threadIdx.x;
    const int bid = blockIdx.x;

    if (bid >= T_BLOCKS) {
        // ---- W -> fp16 conversion ----
        size_t i = (size_t)(bid - T_BLOCKS) * 256 + tid;
        float4 v = W[i];
        __half2* hi = reinterpret_cast<__half2*>(g_whi);
        hi[2 * i]     = __halves2half2(__float2half(v.x), __float2half(v.y));
        hi[2 * i + 1] = __halves2half2(__float2half(v.z), __float2half(v.w));
        return;
    }

    // ---- T partial block ----
    float* xm = reinterpret_cast<float*>(tsm);
    float4* a_sm = reinterpret_cast<float4*>(tsm + T_XM_ELEMS * 4);
    const int slice = bid >> 7;            // 0..3
    const int m0 = (bid & 127) * 64;
    const int kbase = slice * (K_ALL / TSLICES);
    const int mq = tid >> 3;               // 0..31 -> rows 2mq, 2mq+1
    const int rg = tid & 7;
    float acc[2][4];
#pragma unroll
    for (int u = 0; u < 2; ++u)
#pragma unroll
        for (int j = 0; j < 4; ++j) acc[u][j] = 0.f;

    const float4* x4 = reinterpret_cast<const float4*>(x);
    const float4* m4 = reinterpret_cast<const float4*>(mask);
    __half2* xh2 = reinterpret_cast<__half2*>(g_xhi);

    for (int kc = 0; kc < K_ALL / TSLICES; kc += 128) {
        __syncthreads();
#pragma unroll
        for (int i = 0; i < 8; ++i) {             // 2048 float4: 64 rows x 32 f4
            int idx = tid + i * 256;
            int row = idx >> 5, c4 = idx & 31;
            size_t g = ((size_t)(m0 + row) * K_ALL + kbase + kc) / 4 + c4;
            float4 xv = x4[g];
            float4 mv = m4[g];
            // fused x -> fp16 (each (m,k) covered exactly once globally)
            xh2[2 * g]     = __halves2half2(__float2half(xv.x), __float2half(xv.y));
            xh2[2 * g + 1] = __halves2half2(__float2half(xv.z), __float2half(xv.w));
            float* dst = &xm[row * 132 + c4 * 4];
            dst[0] = xv.x * mv.x; dst[1] = xv.y * mv.y;
            dst[2] = xv.z * mv.z; dst[3] = xv.w * mv.w;
        }
        const float4* a4 = reinterpret_cast<const float4*>(A) + (size_t)(kbase + kc) * 8;
#pragma unroll
        for (int i = 0; i < 4; ++i) a_sm[tid + i * 256] = a4[tid + i * 256];
        __syncthreads();
#pragma unroll 4
        for (int k = 0; k < 128; ++k) {
            float4 av = a_sm[k * 8 + rg];
            float x0 = xm[(mq * 2) * 132 + k];
            float x1 = xm[(mq * 2 + 1) * 132 + k];
            acc[0][0] += x0 * av.x; acc[0][1] += x0 * av.y;
            acc[0][2] += x0 * av.z; acc[0][3] += x0 * av.w;
            acc[1][0] += x1 * av.x; acc[1][1] += x1 * av.y;
            acc[1][2] += x1 * av.z; acc[1][3] += x1 * av.w;
        }
    }
#pragma unroll
    for (int u = 0; u < 2; ++u) {
        float* dst = &g_tpart[slice][m0 + mq * 2 + u][rg * 4];
        dst[0] = acc[u][0]; dst[1] = acc[u][1]; dst[2] = acc[u][2]; dst[3] = acc[u][3];
    }
}

// ---------------- kernel #2: B pack (16 blocks) + t_pack (256 blocks) ----------
__global__ void __launch_bounds__(256) prep2_kernel(const float* __restrict__ Bm) {
    const int b = blockIdx.x;
    const int tid = threadIdx.x;
    if (b < 16) {
        int n = b * 256 + tid;
        __half* row = g_btcat + (size_t)n * 64;
#pragma unroll
        for (int r = 0; r < RNK; ++r) {
            __half h = __float2half(Bm[(size_t)r * N_ALL + n]);
            row[r] = h; row[32 + r] = h;
        }
    } else {
        int idx = (b - 16) * 256 + tid;          // 65536 = 8192 m x 8 rgroups
        int m = idx >> 3, rg = idx & 7, r = rg * 4;
        __half* row = g_tcat + (size_t)m * 64;
#pragma unroll
        for (int j = 0; j < 4; ++j) {
            float s = 0.f;
#pragma unroll
            for (int sl = 0; sl < TSLICES; ++sl) s += g_tpart[sl][m][r + j];
            __half h, l;
            split1h(s, h, l);
            row[r + j] = h; row[32 + r + j] = l;
        }
    }
}

// ---------------- fused GEMM ---------------------------------------------------
// CTA tile 128x128, 256 threads (8 warps = 2M x 4N, warp tile 64x32), 2 CTAs/SM.
// 65 K-chunks of 64:  [0,64): xh@Wh   [64]: [Th|Tl]@[Bh|Bh]
#define NCHUNK 65
#define PITCH_B 144
#define A_BYTES (128 * PITCH_B)
#define B_BYTES (128 * PITCH_B)
#define STAGE_BYTES (A_BYTES + B_BYTES)  // 36864
#define NSTAGE 3
#define GEMM_SMEM (NSTAGE * STAGE_BYTES) // 110592

__device__ __forceinline__ void chunk_src(int c, const __half*& pa, const __half*& pb,
                                          int& lda, int& ldb, int& k0) {
    if (c < 64) { pa = g_xhi;  pb = g_whi;   lda = K_ALL; ldb = K_ALL; k0 = c << 6; }
    else        { pa = g_tcat; pb = g_btcat; lda = 64;    ldb = 64;    k0 = 0; }
}

__device__ __forceinline__ void load_chunk(int c, int stage, int tid, int m0, int n0,
                                           uint32_t smem_base) {
    const __half *pa, *pb; int lda, ldb, k0;
    chunk_src(c, pa, pb, lda, ldb, k0);
    uint32_t sA = smem_base + stage * STAGE_BYTES;
    uint32_t sB = sA + A_BYTES;
#pragma unroll
    for (int i = 0; i < 4; ++i) {
        int op = tid + i * 256;
        int row = op >> 3, col = op & 7;
        CP_ASYNC16(sA + (uint32_t)(row * PITCH_B + col * 16),
                   pa + (size_t)(m0 + row) * lda + k0 + col * 8);
        CP_ASYNC16(sB + (uint32_t)(row * PITCH_B + col * 16),
                   pb + (size_t)(n0 + row) * ldb + k0 + col * 8);
    }
}

// one quarter of a chunk's loads (1 A + 1 B cp.async per thread)
__device__ __forceinline__ void load_chunk_part(int c, int stage, int tid, int m0, int n0,
                                                uint32_t smem_base, int part) {
    const __half *pa, *pb; int lda, ldb, k0;
    chunk_src(c, pa, pb, lda, ldb, k0);
    uint32_t sA = smem_base + stage * STAGE_BYTES;
    uint32_t sB = sA + A_BYTES;
    int op = tid + part * 256;
    int row = op >> 3, col = op & 7;
    CP_ASYNC16(sA + (uint32_t)(row * PITCH_B + col * 16),
               pa + (size_t)(m0 + row) * lda + k0 + col * 8);
    CP_ASYNC16(sB + (uint32_t)(row * PITCH_B + col * 16),
               pb + (size_t)(n0 + row) * ldb + k0 + col * 8);
}

// kernel #3: the GEMM
__global__ void __launch_bounds__(256, 2)
lora_gemm_kernel(float* __restrict__ out) {
    extern __shared__ __align__(1024) char smem[];
    const uint32_t smem_base = smem_u32(smem);
    const int tid = threadIdx.x;
    const int wid = tid >> 5;
    const int lane = tid & 31;
    // raster: groups of 16 m-tiles x 32 n-tiles
    const int gid = blockIdx.x >> 9;
    const int rr  = blockIdx.x & 511;
    const int m0 = (gid * 16 + (rr & 15)) * 128;
    const int n0 = (rr >> 4) * 128;
    const int m_w = (wid >> 2) * 64;
    const int n_w = (wid & 3) * 32;

    uint32_t aoff[4];
#pragma unroll
    for (int f = 0; f < 4; ++f)
        aoff[f] = (uint32_t)((m_w + f * 16 + (lane & 15)) * PITCH_B + (lane >> 4) * 16);
    uint32_t boff[2];
#pragma unroll
    for (int jj = 0; jj < 2; ++jj)
        boff[jj] = (uint32_t)(A_BYTES +
                              (n_w + jj * 16 + ((lane >> 4) << 3) + (lane & 7)) * PITCH_B +
                              ((lane >> 3) & 1) * 16);

    float acc[4][4][4];
#pragma unroll
    for (int f = 0; f < 4; ++f)
#pragma unroll
        for (int j = 0; j < 4; ++j)
#pragma unroll
            for (int v = 0; v < 4; ++v) acc[f][j][v] = 0.f;

    load_chunk(0, 0, tid, m0, n0, smem_base);
    CP_ASYNC_COMMIT();
    load_chunk(1, 1, tid, m0, n0, smem_base);
    CP_ASYNC_COMMIT();

    int st_c = 0, st_l = 2;
    for (int c = 0; c < NCHUNK; ++c) {
        CP_ASYNC_WAIT(1);
        __syncthreads();
        const int cl = c + 2;
        const uint32_t sbase = smem_base + st_c * STAGE_BYTES;

        // per-ks interleave; next chunk's cp.async spread 2-per-ks slot
#pragma unroll
        for (int ks = 0; ks < 4; ++ks) {
            uint32_t a[4][4], b[2][4];
#pragma unroll
            for (int jj = 0; jj < 2; ++jj) ldmatrix_x4(b[jj], sbase + boff[jj] + ks * 32);
#pragma unroll
            for (int f = 0; f < 4; ++f) ldmatrix_x4(a[f], sbase + aoff[f] + ks * 32);
            if (cl < NCHUNK) load_chunk_part(cl, st_l, tid, m0, n0, smem_base, ks);
#pragma unroll
            for (int f = 0; f < 4; ++f)
#pragma unroll
                for (int j = 0; j < 4; ++j)
                    mma_fp16(acc[f][j], a[f], b[j >> 1][(j & 1) * 2], b[j >> 1][(j & 1) * 2 + 1]);
        }
        CP_ASYNC_COMMIT();
        st_c = (st_c + 1 == NSTAGE) ? 0 : st_c + 1;
        st_l = (st_l + 1 == NSTAGE) ? 0 : st_l + 1;
    }

    // epilogue
    const int g8 = lane >> 2;
    const int t4 = lane & 3;
#pragma unroll
    for (int f = 0; f < 4; ++f) {
        const int mrow = m0 + m_w + f * 16 + g8;
#pragma unroll
        for (int j = 0; j < 4; ++j) {
            const int ncol = n0 + n_w + j * 8 + t4 * 2;
            float2 v0 = make_float2(acc[f][j][0], acc[f][j][1]);
            float2 v1 = make_float2(acc[f][j][2], acc[f][j][3]);
            *reinterpret_cast<float2*>(out + (size_t)mrow * N_ALL + ncol) = v0;
            *reinterpret_cast<float2*>(out + (size_t)(mrow + 8) * N_ALL + ncol) = v1;
        }
    }
}

// ---------------- launch ---------------------------------------------------------
extern "C" void kernel_launch(void* const* d_in, const int* in_sizes, int n_in,
                              void* d_out, int out_size) {
    const float* x    = (const float*)d_in[0];   // [8192, 4096]
    const float* W    = (const float*)d_in[1];   // [4096, 4096]
    const float* A    = (const float*)d_in[2];   // [4096, 32]
    const float* Bm   = (const float*)d_in[3];   // [32, 4096]
    const float* mask = (const float*)d_in[4];   // [8192, 4096]
    float* out = (float*)d_out;

    static bool attr_set = false;
    if (!attr_set) {
        cudaFuncSetAttribute(lora_gemm_kernel,
                             cudaFuncAttributeMaxDynamicSharedMemorySize, GEMM_SMEM);
        cudaFuncSetAttribute(prep1_kernel,
                             cudaFuncAttributeMaxDynamicSharedMemorySize, T_SMEM_BYTES);
        attr_set = true;
    }

    prep1_kernel<<<T_BLOCKS + W_BLOCKS, 256, T_SMEM_BYTES>>>(x, mask, A, (const float4*)W);
    prep2_kernel<<<272, 256>>>(Bm);
    lora_gemm_kernel<<<2048, 256, GEMM_SMEM>>>(out);
}

// round 11
// speedup vs baseline: 3.3576x; 1.0226x over previous
#include <cuda_runtime.h>
#include <cuda_fp16.h>
#include <cstdint>

// out[8192,4096] = x@W^T + ((x*mask)@A)@B   (fp32, SCALE=1)
// Single-pass fp16: xh=fp16(x), Wh=fp16(W). LoRA band exact-T: [Th|Tl]@[Bh|Bh].
#define M_ALL 8192
#define N_ALL 4096
#define K_ALL 4096
#define RNK   32
#define TSLICES 4

// ---------------- scratch (__device__ globals; no allocs allowed) ------------
__device__ __align__(256) __half g_xhi[(size_t)M_ALL * K_ALL];
__device__ __align__(256) __half g_whi[(size_t)N_ALL * K_ALL];
__device__ __align__(256) __half g_tcat[(size_t)M_ALL * 64];    // [Th|Tl]
__device__ __align__(256) __half g_btcat[(size_t)N_ALL * 64];   // [Bh|Bh]
__device__ __align__(256) float g_tpart[TSLICES][M_ALL][RNK];

// ---------------- PTX helpers -------------------------------------------------
__device__ __forceinline__ uint32_t smem_u32(const void* p) {
    uint32_t a;
    asm("{ .reg .u64 t; cvta.to.shared.u64 t, %1; cvt.u32.u64 %0, t; }" : "=r"(a) : "l"(p));
    return a;
}
#define CP_ASYNC16(dst, src) \
    asm volatile("cp.async.cg.shared.global [%0], [%1], 16;" :: "r"((uint32_t)(dst)), "l"(src))
#define CP_ASYNC_COMMIT() asm volatile("cp.async.commit_group;" ::: "memory")
#define CP_ASYNC_WAIT(n)  asm volatile("cp.async.wait_group %0;" :: "n"(n) : "memory")

__device__ __forceinline__ void ldmatrix_x4(uint32_t* r, uint32_t addr) {
    asm volatile("ldmatrix.sync.aligned.m8n8.x4.shared.b16 {%0,%1,%2,%3}, [%4];"
                 : "=r"(r[0]), "=r"(r[1]), "=r"(r[2]), "=r"(r[3]) : "r"(addr));
}
__device__ __forceinline__ void mma_fp16(float* d, const uint32_t* a, uint32_t b0, uint32_t b1) {
    asm volatile(
        "mma.sync.aligned.m16n8k16.row.col.f32.f16.f16.f32 "
        "{%0,%1,%2,%3}, {%4,%5,%6,%7}, {%8,%9}, {%0,%1,%2,%3};"
        : "+f"(d[0]), "+f"(d[1]), "+f"(d[2]), "+f"(d[3])
        : "r"(a[0]), "r"(a[1]), "r"(a[2]), "r"(a[3]), "r"(b0), "r"(b1));
}
__device__ __forceinline__ void split1h(float v, __half& h, __half& l) {
    h = __float2half(v);
    l = __float2half(v - __half2float(h));
}

// ---------------- kernel #1: T partials + x->fp16 + W->fp16 (merged grid) ------
// bid < 512: t-block (64 m-rows, K-slice 1024, fused x conversion)
// bid >= 512: W conversion block (4 float4 per thread for MLP)
#define T_BLOCKS 512
#define W_BLOCKS 4096
#define T_XM_ELEMS (64 * 132)
#define T_SMEM_BYTES (T_XM_ELEMS * 4 + 128 * 8 * 16)   // 50176
__global__ void __launch_bounds__(256) prep1_kernel(const float* __restrict__ x,
                                                    const float* __restrict__ mask,
                                                    const float* __restrict__ A,
                                                    const float4* __restrict__ W) {
    extern __shared__ __align__(16) char tsm[];
    const int tid = threadIdx.x;
    const int bid = blockIdx.x;

    if (bid >= T_BLOCKS) {
        // ---- W -> fp16 conversion, 4 float4 per thread (MLP=4) ----
        size_t base = (size_t)(bid - T_BLOCKS) * 1024 + tid;
        __half2* hi = reinterpret_cast<__half2*>(g_whi);
        float4 v[4];
#pragma unroll
        for (int u = 0; u < 4; ++u) v[u] = W[base + u * 256];
#pragma unroll
        for (int u = 0; u < 4; ++u) {
            size_t i = base + u * 256;
            hi[2 * i]     = __halves2half2(__float2half(v[u].x), __float2half(v[u].y));
            hi[2 * i + 1] = __halves2half2(__float2half(v[u].z), __float2half(v[u].w));
        }
        return;
    }

    // ---- T partial block ----
    float* xm = reinterpret_cast<float*>(tsm);
    float4* a_sm = reinterpret_cast<float4*>(tsm + T_XM_ELEMS * 4);
    const int slice = bid >> 7;            // 0..3
    const int m0 = (bid & 127) * 64;
    const int kbase = slice * (K_ALL / TSLICES);
    const int mq = tid >> 3;               // 0..31 -> rows 2mq, 2mq+1
    const int rg = tid & 7;
    float acc[2][4];
#pragma unroll
    for (int u = 0; u < 2; ++u)
#pragma unroll
        for (int j = 0; j < 4; ++j) acc[u][j] = 0.f;

    const float4* x4 = reinterpret_cast<const float4*>(x);
    const float4* m4 = reinterpret_cast<const float4*>(mask);
    __half2* xh2 = reinterpret_cast<__half2*>(g_xhi);

    for (int kc = 0; kc < K_ALL / TSLICES; kc += 128) {
        __syncthreads();
#pragma unroll
        for (int i = 0; i < 8; ++i) {             // 2048 float4: 64 rows x 32 f4
            int idx = tid + i * 256;
            int row = idx >> 5, c4 = idx & 31;
            size_t g = ((size_t)(m0 + row) * K_ALL + kbase + kc) / 4 + c4;
            float4 xv = x4[g];
            float4 mv = m4[g];
            // fused x -> fp16 (each (m,k) covered exactly once globally)
            xh2[2 * g]     = __halves2half2(__float2half(xv.x), __float2half(xv.y));
            xh2[2 * g + 1] = __halves2half2(__float2half(xv.z), __float2half(xv.w));
            float* dst = &xm[row * 132 + c4 * 4];
            dst[0] = xv.x * mv.x; dst[1] = xv.y * mv.y;
            dst[2] = xv.z * mv.z; dst[3] = xv.w * mv.w;
        }
        const float4* a4 = reinterpret_cast<const float4*>(A) + (size_t)(kbase + kc) * 8;
#pragma unroll
        for (int i = 0; i < 4; ++i) a_sm[tid + i * 256] = a4[tid + i * 256];
        __syncthreads();
#pragma unroll 4
        for (int k = 0; k < 128; ++k) {
            float4 av = a_sm[k * 8 + rg];
            float x0 = xm[(mq * 2) * 132 + k];
            float x1 = xm[(mq * 2 + 1) * 132 + k];
            acc[0][0] += x0 * av.x; acc[0][1] += x0 * av.y;
            acc[0][2] += x0 * av.z; acc[0][3] += x0 * av.w;
            acc[1][0] += x1 * av.x; acc[1][1] += x1 * av.y;
            acc[1][2] += x1 * av.z; acc[1][3] += x1 * av.w;
        }
    }
#pragma unroll
    for (int u = 0; u < 2; ++u) {
        float* dst = &g_tpart[slice][m0 + mq * 2 + u][rg * 4];
        dst[0] = acc[u][0]; dst[1] = acc[u][1]; dst[2] = acc[u][2]; dst[3] = acc[u][3];
    }
}

// ---------------- kernel #2: B pack (16 blocks) + t_pack (256 blocks) ----------
__global__ void __launch_bounds__(256) prep2_kernel(const float* __restrict__ Bm) {
    const int b = blockIdx.x;
    const int tid = threadIdx.x;
    if (b < 16) {
        int n = b * 256 + tid;
        __half* row = g_btcat + (size_t)n * 64;
#pragma unroll
        for (int r = 0; r < RNK; ++r) {
            __half h = __float2half(Bm[(size_t)r * N_ALL + n]);
            row[r] = h; row[32 + r] = h;
        }
    } else {
        int idx = (b - 16) * 256 + tid;          // 65536 = 8192 m x 8 rgroups
        int m = idx >> 3, rg = idx & 7, r = rg * 4;
        __half* row = g_tcat + (size_t)m * 64;
#pragma unroll
        for (int j = 0; j < 4; ++j) {
            float s = 0.f;
#pragma unroll
            for (int sl = 0; sl < TSLICES; ++sl) s += g_tpart[sl][m][r + j];
            __half h, l;
            split1h(s, h, l);
            row[r + j] = h; row[32 + r + j] = l;
        }
    }
}

// ---------------- fused GEMM ---------------------------------------------------
// CTA tile 128x128, 256 threads (8 warps = 2M x 4N, warp tile 64x32), 2 CTAs/SM.
// 65 K-chunks of 64:  [0,64): xh@Wh   [64]: [Th|Tl]@[Bh|Bh]
#define NCHUNK 65
#define PITCH_B 144
#define A_BYTES (128 * PITCH_B)
#define B_BYTES (128 * PITCH_B)
#define STAGE_BYTES (A_BYTES + B_BYTES)  // 36864
#define NSTAGE 3
#define GEMM_SMEM (NSTAGE * STAGE_BYTES) // 110592

__device__ __forceinline__ void load_chunk(int c, int stage, int tid, int m0, int n0,
                                           uint32_t smem_base) {
    const __half *pa, *pb;
    int lda, ldb, k0;
    if (c < 64) { pa = g_xhi;  pb = g_whi;   lda = K_ALL; ldb = K_ALL; k0 = c << 6; }
    else        { pa = g_tcat; pb = g_btcat; lda = 64;    ldb = 64;    k0 = 0; }
    uint32_t sA = smem_base + stage * STAGE_BYTES;
    uint32_t sB = sA + A_BYTES;
#pragma unroll
    for (int i = 0; i < 4; ++i) {
        int op = tid + i * 256;
        int row = op >> 3, col = op & 7;
        CP_ASYNC16(sA + (uint32_t)(row * PITCH_B + col * 16),
                   pa + (size_t)(m0 + row) * lda + k0 + col * 8);
        CP_ASYNC16(sB + (uint32_t)(row * PITCH_B + col * 16),
                   pb + (size_t)(n0 + row) * ldb + k0 + col * 8);
    }
}

// kernel #3: the GEMM
__global__ void __launch_bounds__(256, 2)
lora_gemm_kernel(float* __restrict__ out) {
    extern __shared__ __align__(1024) char smem[];
    const uint32_t smem_base = smem_u32(smem);
    const int tid = threadIdx.x;
    const int wid = tid >> 5;
    const int lane = tid & 31;
    // raster: groups of 16 m-tiles x 32 n-tiles
    const int gid = blockIdx.x >> 9;
    const int rr  = blockIdx.x & 511;
    const int m0 = (gid * 16 + (rr & 15)) * 128;
    const int n0 = (rr >> 4) * 128;
    const int m_w = (wid >> 2) * 64;
    const int n_w = (wid & 3) * 32;

    uint32_t aoff[4];
#pragma unroll
    for (int f = 0; f < 4; ++f)
        aoff[f] = (uint32_t)((m_w + f * 16 + (lane & 15)) * PITCH_B + (lane >> 4) * 16);
    uint32_t boff[2];
#pragma unroll
    for (int jj = 0; jj < 2; ++jj)
        boff[jj] = (uint32_t)(A_BYTES +
                              (n_w + jj * 16 + ((lane >> 4) << 3) + (lane & 7)) * PITCH_B +
                              ((lane >> 3) & 1) * 16);

    float acc[4][4][4];
#pragma unroll
    for (int f = 0; f < 4; ++f)
#pragma unroll
        for (int j = 0; j < 4; ++j)
#pragma unroll
            for (int v = 0; v < 4; ++v) acc[f][j][v] = 0.f;

    load_chunk(0, 0, tid, m0, n0, smem_base);
    CP_ASYNC_COMMIT();
    load_chunk(1, 1, tid, m0, n0, smem_base);
    CP_ASYNC_COMMIT();

    int st_c = 0, st_l = 2;
    for (int c = 0; c < NCHUNK; ++c) {
        CP_ASYNC_WAIT(1);
        __syncthreads();
        const int cl = c + 2;
        const uint32_t sbase = smem_base + st_c * STAGE_BYTES;

        // per-ks interleave: ld frags(ks) -> mma(ks); next chunk's cp.async issued
        // once, in the ks==1 slot (inside the mma shadow) — R8 scheme.
#pragma unroll
        for (int ks = 0; ks < 4; ++ks) {
            uint32_t a[4][4], b[2][4];
#pragma unroll
            for (int jj = 0; jj < 2; ++jj) ldmatrix_x4(b[jj], sbase + boff[jj] + ks * 32);
#pragma unroll
            for (int f = 0; f < 4; ++f) ldmatrix_x4(a[f], sbase + aoff[f] + ks * 32);
            if (ks == 1 && cl < NCHUNK) load_chunk(cl, st_l, tid, m0, n0, smem_base);
#pragma unroll
            for (int f = 0; f < 4; ++f)
#pragma unroll
                for (int j = 0; j < 4; ++j)
                    mma_fp16(acc[f][j], a[f], b[j >> 1][(j & 1) * 2], b[j >> 1][(j & 1) * 2 + 1]);
        }
        CP_ASYNC_COMMIT();
        st_c = (st_c + 1 == NSTAGE) ? 0 : st_c + 1;
        st_l = (st_l + 1 == NSTAGE) ? 0 : st_l + 1;
    }

    // epilogue
    const int g8 = lane >> 2;
    const int t4 = lane & 3;
#pragma unroll
    for (int f = 0; f < 4; ++f) {
        const int mrow = m0 + m_w + f * 16 + g8;
#pragma unroll
        for (int j = 0; j < 4; ++j) {
            const int ncol = n0 + n_w + j * 8 + t4 * 2;
            float2 v0 = make_float2(acc[f][j][0], acc[f][j][1]);
            float2 v1 = make_float2(acc[f][j][2], acc[f][j][3]);
            *reinterpret_cast<float2*>(out + (size_t)mrow * N_ALL + ncol) = v0;
            *reinterpret_cast<float2*>(out + (size_t)(mrow + 8) * N_ALL + ncol) = v1;
        }
    }
}

// ---------------- launch ---------------------------------------------------------
extern "C" void kernel_launch(void* const* d_in, const int* in_sizes, int n_in,
                              void* d_out, int out_size) {
    const float* x    = (const float*)d_in[0];   // [8192, 4096]
    const float* W    = (const float*)d_in[1];   // [4096, 4096]
    const float* A    = (const float*)d_in[2];   // [4096, 32]
    const float* Bm   = (const float*)d_in[3];   // [32, 4096]
    const float* mask = (const float*)d_in[4];   // [8192, 4096]
    float* out = (float*)d_out;

    static bool attr_set = false;
    if (!attr_set) {
        cudaFuncSetAttribute(lora_gemm_kernel,
                             cudaFuncAttributeMaxDynamicSharedMemorySize, GEMM_SMEM);
        cudaFuncSetAttribute(prep1_kernel,
                             cudaFuncAttributeMaxDynamicSharedMemorySize, T_SMEM_BYTES);
        attr_set = true;
    }

    prep1_kernel<<<T_BLOCKS + W_BLOCKS, 256, T_SMEM_BYTES>>>(x, mask, A, (const float4*)W);
    prep2_kernel<<<272, 256>>>(Bm);
    lora_gemm_kernel<<<2048, 256, GEMM_SMEM>>>(out);
}

// round 12
// speedup vs baseline: 3.3998x; 1.0126x over previous
#include <cuda_runtime.h>
#include <cuda_fp16.h>
#include <cstdint>

// out[8192,4096] = x@W^T + ((x*mask)@A)@B   (fp32, SCALE=1)
// fp16 single-pass main GEMM; LoRA T via fp16 tensor-core GEMM (fp32 accum).
#define M_ALL 8192
#define N_ALL 4096
#define K_ALL 4096
#define RNK   32
#define TSLICES 4          // K-slices per t-block grid dim
#define TP_SLICES 8        // TSLICES * 2 k-halves (per-warp split)

// ---------------- scratch (__device__ globals; no allocs allowed) ------------
__device__ __align__(256) __half g_xhi[(size_t)M_ALL * K_ALL];
__device__ __align__(256) __half g_whi[(size_t)N_ALL * K_ALL];
__device__ __align__(256) __half g_tcat[(size_t)M_ALL * 64];    // [Th|Tl]
__device__ __align__(256) __half g_btcat[(size_t)N_ALL * 64];   // [Bh|Bh]
__device__ __align__(256) float g_tpart[TP_SLICES][M_ALL][RNK];

// ---------------- PTX helpers -------------------------------------------------
__device__ __forceinline__ uint32_t smem_u32(const void* p) {
    uint32_t a;
    asm("{ .reg .u64 t; cvta.to.shared.u64 t, %1; cvt.u32.u64 %0, t; }" : "=r"(a) : "l"(p));
    return a;
}
#define CP_ASYNC16(dst, src) \
    asm volatile("cp.async.cg.shared.global [%0], [%1], 16;" :: "r"((uint32_t)(dst)), "l"(src))
#define CP_ASYNC_COMMIT() asm volatile("cp.async.commit_group;" ::: "memory")
#define CP_ASYNC_WAIT(n)  asm volatile("cp.async.wait_group %0;" :: "n"(n) : "memory")

__device__ __forceinline__ void ldmatrix_x4(uint32_t* r, uint32_t addr) {
    asm volatile("ldmatrix.sync.aligned.m8n8.x4.shared.b16 {%0,%1,%2,%3}, [%4];"
                 : "=r"(r[0]), "=r"(r[1]), "=r"(r[2]), "=r"(r[3]) : "r"(addr));
}
__device__ __forceinline__ void mma_fp16(float* d, const uint32_t* a, uint32_t b0, uint32_t b1) {
    asm volatile(
        "mma.sync.aligned.m16n8k16.row.col.f32.f16.f16.f32 "
        "{%0,%1,%2,%3}, {%4,%5,%6,%7}, {%8,%9}, {%0,%1,%2,%3};"
        : "+f"(d[0]), "+f"(d[1]), "+f"(d[2]), "+f"(d[3])
        : "r"(a[0]), "r"(a[1]), "r"(a[2]), "r"(a[3]), "r"(b0), "r"(b1));
}
__device__ __forceinline__ void split1h(float v, __half& h, __half& l) {
    h = __float2half(v);
    l = __float2half(v - __half2float(h));
}

// ---------------- kernel #1: T partials (tensor core) + x->fp16 + W->fp16 ------
// bid < 512: t-block (64 m-rows, K-slice 1024, fused x conversion, fp16 mma)
// bid >= 512: W conversion block (4 float4 per thread)
#define T_BLOCKS 512
#define W_BLOCKS 4096
#define TP_PITCH 272                       // bytes per smem row (128 k fp16 + pad)
#define TP_XM_BYTES (64 * TP_PITCH)        // 17408
#define TP_AT_BYTES (32 * TP_PITCH)        // 8704
#define T_SMEM_BYTES (TP_XM_BYTES + TP_AT_BYTES)   // 26112

__global__ void __launch_bounds__(256) prep1_kernel(const float* __restrict__ x,
                                                    const float* __restrict__ mask,
                                                    const float* __restrict__ A,
                                                    const float4* __restrict__ W) {
    extern __shared__ __align__(16) char tsm[];
    const int tid = threadIdx.x;
    const int bid = blockIdx.x;

    if (bid >= T_BLOCKS) {
        // ---- W -> fp16 conversion, 4 float4 per thread (MLP=4) ----
        size_t base = (size_t)(bid - T_BLOCKS) * 1024 + tid;
        __half2* hi = reinterpret_cast<__half2*>(g_whi);
        float4 v[4];
#pragma unroll
        for (int u = 0; u < 4; ++u) v[u] = W[base + u * 256];
#pragma unroll
        for (int u = 0; u < 4; ++u) {
            size_t i = base + u * 256;
            hi[2 * i]     = __halves2half2(__float2half(v[u].x), __float2half(v[u].y));
            hi[2 * i + 1] = __halves2half2(__float2half(v[u].z), __float2half(v[u].w));
        }
        return;
    }

    // ---- T partial block: 64 m-rows x 32 r over a 1024-wide K slice ----
    const uint32_t smem_base = smem_u32(tsm);
    const uint32_t xm_base = smem_base;
    const uint32_t at_base = smem_base + TP_XM_BYTES;
    const int wid = tid >> 5;
    const int lane = tid & 31;
    const int slice = bid >> 7;            // 0..3
    const int m0 = (bid & 127) * 64;
    const int kbase = slice * (K_ALL / TSLICES);
    const int mw = (wid & 3) * 16;         // warp m-tile
    const int kh = wid >> 2;               // warp k-half (0: k 0-63, 1: k 64-127)

    // fragment addresses (mirror main-GEMM scheme)
    const uint32_t a_addr = xm_base + (uint32_t)(mw + (lane & 15)) * TP_PITCH +
                            (uint32_t)((lane >> 4) * 16 + kh * 128);
    uint32_t b_addr[2];
#pragma unroll
    for (int jj = 0; jj < 2; ++jj)
        b_addr[jj] = at_base +
                     (uint32_t)(jj * 16 + ((lane >> 4) << 3) + (lane & 7)) * TP_PITCH +
                     (uint32_t)(((lane >> 3) & 1) * 16 + kh * 128);

    float acc[4][4];
#pragma unroll
    for (int j = 0; j < 4; ++j)
#pragma unroll
        for (int v = 0; v < 4; ++v) acc[j][v] = 0.f;

    const float4* x4 = reinterpret_cast<const float4*>(x);
    const float4* m4 = reinterpret_cast<const float4*>(mask);
    __half2* xh2 = reinterpret_cast<__half2*>(g_xhi);

    for (int kc = 0; kc < K_ALL / TSLICES; kc += 128) {
        __syncthreads();
        // load x*mask -> xm (fp16), fused unmasked x -> g_xhi
#pragma unroll
        for (int i = 0; i < 8; ++i) {             // 2048 float4: 64 rows x 32 f4
            int idx = tid + i * 256;
            int row = idx >> 5, c4 = idx & 31;
            size_t g = ((size_t)(m0 + row) * K_ALL + kbase + kc) / 4 + c4;
            float4 xv = x4[g];
            float4 mv = m4[g];
            xh2[2 * g]     = __halves2half2(__float2half(xv.x), __float2half(xv.y));
            xh2[2 * g + 1] = __halves2half2(__float2half(xv.z), __float2half(xv.w));
            __half2* dst = reinterpret_cast<__half2*>(tsm + row * TP_PITCH + c4 * 8);
            dst[0] = __halves2half2(__float2half(xv.x * mv.x), __float2half(xv.y * mv.y));
            dst[1] = __halves2half2(__float2half(xv.z * mv.z), __float2half(xv.w * mv.w));
        }
        // A chunk transpose: a_smT[r][kk] = fp16(A[kbase+kc+kk][r])
#pragma unroll
        for (int i = 0; i < 16; ++i) {            // 4096 elems
            int idx = tid + i * 256;
            int kk = idx >> 5, r = idx & 31;
            *reinterpret_cast<__half*>(tsm + TP_XM_BYTES + r * TP_PITCH + kk * 2) =
                __float2half(A[(size_t)(kbase + kc + kk) * RNK + r]);
        }
        __syncthreads();
        // tensor-core partial: 4 k-steps of 16 over this warp's 64-k half
#pragma unroll
        for (int ks = 0; ks < 4; ++ks) {
            uint32_t a[4], b[2][4];
            ldmatrix_x4(a, a_addr + ks * 32);
            ldmatrix_x4(b[0], b_addr[0] + ks * 32);
            ldmatrix_x4(b[1], b_addr[1] + ks * 32);
#pragma unroll
            for (int j = 0; j < 4; ++j)
                mma_fp16(acc[j], a, b[j >> 1][(j & 1) * 2], b[j >> 1][(j & 1) * 2 + 1]);
        }
    }
    // store partials: slice index = slice*2 + kh
    const int sl = slice * 2 + kh;
    const int g8 = lane >> 2;
    const int t4 = lane & 3;
#pragma unroll
    for (int j = 0; j < 4; ++j) {
        int r = j * 8 + t4 * 2;
        int m = m0 + mw + g8;
        *reinterpret_cast<float2*>(&g_tpart[sl][m][r]) = make_float2(acc[j][0], acc[j][1]);
        *reinterpret_cast<float2*>(&g_tpart[sl][m + 8][r]) = make_float2(acc[j][2], acc[j][3]);
    }
}

// ---------------- kernel #2: B pack (16 blocks) + t_pack (256 blocks) ----------
__global__ void __launch_bounds__(256) prep2_kernel(const float* __restrict__ Bm) {
    const int b = blockIdx.x;
    const int tid = threadIdx.x;
    if (b < 16) {
        int n = b * 256 + tid;
        __half* row = g_btcat + (size_t)n * 64;
#pragma unroll
        for (int r = 0; r < RNK; ++r) {
            __half h = __float2half(Bm[(size_t)r * N_ALL + n]);
            row[r] = h; row[32 + r] = h;
        }
    } else {
        int idx = (b - 16) * 256 + tid;          // 65536 = 8192 m x 8 rgroups
        int m = idx >> 3, rg = idx & 7, r = rg * 4;
        __half* row = g_tcat + (size_t)m * 64;
#pragma unroll
        for (int j = 0; j < 4; ++j) {
            float s = 0.f;
#pragma unroll
            for (int sl = 0; sl < TP_SLICES; ++sl) s += g_tpart[sl][m][r + j];
            __half h, l;
            split1h(s, h, l);
            row[r + j] = h; row[32 + r + j] = l;
        }
    }
}

// ---------------- fused GEMM ---------------------------------------------------
// CTA tile 128x128, 256 threads (8 warps = 2M x 4N, warp tile 64x32), 2 CTAs/SM.
// 65 K-chunks of 64:  [0,64): xh@Wh   [64]: [Th|Tl]@[Bh|Bh]
#define NCHUNK 65
#define PITCH_B 144
#define A_BYTES (128 * PITCH_B)
#define B_BYTES (128 * PITCH_B)
#define STAGE_BYTES (A_BYTES + B_BYTES)  // 36864
#define NSTAGE 3
#define GEMM_SMEM (NSTAGE * STAGE_BYTES) // 110592

__device__ __forceinline__ void load_chunk(int c, int stage, int tid, int m0, int n0,
                                           uint32_t smem_base) {
    const __half *pa, *pb;
    int lda, ldb, k0;
    if (c < 64) { pa = g_xhi;  pb = g_whi;   lda = K_ALL; ldb = K_ALL; k0 = c << 6; }
    else        { pa = g_tcat; pb = g_btcat; lda = 64;    ldb = 64;    k0 = 0; }
    uint32_t sA = smem_base + stage * STAGE_BYTES;
    uint32_t sB = sA + A_BYTES;
#pragma unroll
    for (int i = 0; i < 4; ++i) {
        int op = tid + i * 256;
        int row = op >> 3, col = op & 7;
        CP_ASYNC16(sA + (uint32_t)(row * PITCH_B + col * 16),
                   pa + (size_t)(m0 + row) * lda + k0 + col * 8);
        CP_ASYNC16(sB + (uint32_t)(row * PITCH_B + col * 16),
                   pb + (size_t)(n0 + row) * ldb + k0 + col * 8);
    }
}

// kernel #3: the GEMM
__global__ void __launch_bounds__(256, 2)
lora_gemm_kernel(float* __restrict__ out) {
    extern __shared__ __align__(1024) char smem[];
    const uint32_t smem_base = smem_u32(smem);
    const int tid = threadIdx.x;
    const int wid = tid >> 5;
    const int lane = tid & 31;
    // raster: groups of 16 m-tiles x 32 n-tiles
    const int gid = blockIdx.x >> 9;
    const int rr  = blockIdx.x & 511;
    const int m0 = (gid * 16 + (rr & 15)) * 128;
    const int n0 = (rr >> 4) * 128;
    const int m_w = (wid >> 2) * 64;
    const int n_w = (wid & 3) * 32;

    uint32_t aoff[4];
#pragma unroll
    for (int f = 0; f < 4; ++f)
        aoff[f] = (uint32_t)((m_w + f * 16 + (lane & 15)) * PITCH_B + (lane >> 4) * 16);
    uint32_t boff[2];
#pragma unroll
    for (int jj = 0; jj < 2; ++jj)
        boff[jj] = (uint32_t)(A_BYTES +
                              (n_w + jj * 16 + ((lane >> 4) << 3) + (lane & 7)) * PITCH_B +
                              ((lane >> 3) & 1) * 16);

    float acc[4][4][4];
#pragma unroll
    for (int f = 0; f < 4; ++f)
#pragma unroll
        for (int j = 0; j < 4; ++j)
#pragma unroll
            for (int v = 0; v < 4; ++v) acc[f][j][v] = 0.f;

    load_chunk(0, 0, tid, m0, n0, smem_base);
    CP_ASYNC_COMMIT();
    load_chunk(1, 1, tid, m0, n0, smem_base);
    CP_ASYNC_COMMIT();

    int st_c = 0, st_l = 2;
    for (int c = 0; c < NCHUNK; ++c) {
        CP_ASYNC_WAIT(1);
        __syncthreads();
        const int cl = c + 2;
        const uint32_t sbase = smem_base + st_c * STAGE_BYTES;

        // per-ks interleave; next chunk's cp.async in the ks==1 shadow
#pragma unroll
        for (int ks = 0; ks < 4; ++ks) {
            uint32_t a[4][4], b[2][4];
#pragma unroll
            for (int jj = 0; jj < 2; ++jj) ldmatrix_x4(b[jj], sbase + boff[jj] + ks * 32);
#pragma unroll
            for (int f = 0; f < 4; ++f) ldmatrix_x4(a[f], sbase + aoff[f] + ks * 32);
            if (ks == 1 && cl < NCHUNK) load_chunk(cl, st_l, tid, m0, n0, smem_base);
#pragma unroll
            for (int f = 0; f < 4; ++f)
#pragma unroll
                for (int j = 0; j < 4; ++j)
                    mma_fp16(acc[f][j], a[f], b[j >> 1][(j & 1) * 2], b[j >> 1][(j & 1) * 2 + 1]);
        }
        CP_ASYNC_COMMIT();
        st_c = (st_c + 1 == NSTAGE) ? 0 : st_c + 1;
        st_l = (st_l + 1 == NSTAGE) ? 0 : st_l + 1;
    }

    // epilogue
    const int g8 = lane >> 2;
    const int t4 = lane & 3;
#pragma unroll
    for (int f = 0; f < 4; ++f) {
        const int mrow = m0 + m_w + f * 16 + g8;
#pragma unroll
        for (int j = 0; j < 4; ++j) {
            const int ncol = n0 + n_w + j * 8 + t4 * 2;
            float2 v0 = make_float2(acc[f][j][0], acc[f][j][1]);
            float2 v1 = make_float2(acc[f][j][2], acc[f][j][3]);
            *reinterpret_cast<float2*>(out + (size_t)mrow * N_ALL + ncol) = v0;
            *reinterpret_cast<float2*>(out + (size_t)(mrow + 8) * N_ALL + ncol) = v1;
        }
    }
}

// ---------------- launch ---------------------------------------------------------
extern "C" void kernel_launch(void* const* d_in, const int* in_sizes, int n_in,
                              void* d_out, int out_size) {
    const float* x    = (const float*)d_in[0];   // [8192, 4096]
    const float* W    = (const float*)d_in[1];   // [4096, 4096]
    const float* A    = (const float*)d_in[2];   // [4096, 32]
    const float* Bm   = (const float*)d_in[3];   // [32, 4096]
    const float* mask = (const float*)d_in[4];   // [8192, 4096]
    float* out = (float*)d_out;

    static bool attr_set = false;
    if (!attr_set) {
        cudaFuncSetAttribute(lora_gemm_kernel,
                             cudaFuncAttributeMaxDynamicSharedMemorySize, GEMM_SMEM);
        cudaFuncSetAttribute(prep1_kernel,
                             cudaFuncAttributeMaxDynamicSharedMemorySize, T_SMEM_BYTES);
        attr_set = true;
    }

    prep1_kernel<<<T_BLOCKS + W_BLOCKS, 256, T_SMEM_BYTES>>>(x, mask, A, (const float4*)W);
    prep2_kernel<<<272, 256>>>(Bm);
    lora_gemm_kernel<<<2048, 256, GEMM_SMEM>>>(out);
}